// round 3
// baseline (speedup 1.0000x reference)
#include <cuda_runtime.h>
#include <cstddef>

// ---------------------------------------------------------------------------
// Scratch (static __device__ allocations; no cudaMalloc allowed)
// ---------------------------------------------------------------------------
#define BATCH 4096

__device__ float g_h1[(size_t)BATCH * 32 * 26 * 26];   // conv1 out  (354 MB)
__device__ float g_h2[(size_t)BATCH * 64 * 12 * 12];   // conv2+pool (151 MB)
__device__ float g_h3[(size_t)BATCH * 128];            // fc1 out
__device__ float g_sig[10 * 10 * 10];                  // Sigma_inv per component
__device__ float g_det[10];                            // det_scale per component

// ---------------------------------------------------------------------------
// GMM precompute: L = tril(raw,-1)+I ; D = diag(raw)^2 + 1e-4
// Sigma_inv = L^{-T} D^{-1} L^{-1} ; det_scale = rsqrt(prod D)
// ---------------------------------------------------------------------------
__global__ void k_gmm_pre(const float* __restrict__ raw) {
    int k = threadIdx.x;
    if (k >= 10) return;
    const float* R = raw + k * 100;

    float D[10];
#pragma unroll
    for (int i = 0; i < 10; i++) {
        float r = R[i * 10 + i];
        D[i] = r * r + 1e-4f;
    }

    // Unit-lower-triangular inverse via forward substitution.
    float Li[10][10];
#pragma unroll
    for (int i = 0; i < 10; i++)
#pragma unroll
        for (int j = 0; j < 10; j++) Li[i][j] = (i == j) ? 1.f : 0.f;

    for (int j = 0; j < 10; j++) {
        for (int i = j + 1; i < 10; i++) {
            float s = 0.f;
            for (int m = j; m < i; m++) s = fmaf(R[i * 10 + m], Li[m][j], s);
            Li[i][j] = -s;
        }
    }

    for (int i = 0; i < 10; i++) {
        for (int j = 0; j < 10; j++) {
            int a0 = (i > j) ? i : j;
            float s = 0.f;
            for (int a = a0; a < 10; a++) s += Li[a][i] * Li[a][j] / D[a];
            g_sig[k * 100 + i * 10 + j] = s;
        }
    }

    float p = 1.f;
#pragma unroll
    for (int a = 0; a < 10; a++) p *= D[a];
    g_det[k] = rsqrtf(p);
}

// ---------------------------------------------------------------------------
// conv1: [B,1,28,28] -> relu -> [B,32,26,26]
// ---------------------------------------------------------------------------
__global__ void k_conv1(const float* __restrict__ x,
                        const float* __restrict__ w,
                        const float* __restrict__ bias) {
    int t = blockIdx.x * 256 + threadIdx.x;
    const int TOTAL = BATCH * 32 * 26 * 26;   // 88,604,672
    if (t >= TOTAL) return;

    int ox = t % 26;
    int r  = t / 26;
    int oy = r % 26;  r /= 26;
    int c  = r % 32;
    int b  = r / 32;

    const float* xp = x + (size_t)b * 784 + oy * 28 + ox;
    const float* wp = w + c * 9;
    float acc = bias[c];
#pragma unroll
    for (int dy = 0; dy < 3; dy++)
#pragma unroll
        for (int dx = 0; dx < 3; dx++)
            acc = fmaf(xp[dy * 28 + dx], wp[dy * 3 + dx], acc);

    g_h1[t] = fmaxf(acc, 0.f);
}

// ---------------------------------------------------------------------------
// conv2 + relu + 2x2 maxpool (fused): [B,32,26,26] -> [B,64,12,12]
// One block per image. Input image + all weights staged in smem.
// Each thread item: 4 output channels x one 2x2 pool quad (16 accumulators).
// ---------------------------------------------------------------------------
__global__ void k_conv2pool(const float* __restrict__ cw,
                            const float* __restrict__ cb) {
    const int b = blockIdx.x;
    extern __shared__ float sm[];
    float* sIn = sm;               // 32*26*26 = 21632 floats
    float* sW  = sm + 21632;       // 64*32*9  = 18432 floats

    {
        const float4* src = reinterpret_cast<const float4*>(&g_h1[(size_t)b * 21632]);
        float4* dst = reinterpret_cast<float4*>(sIn);
        for (int i = threadIdx.x; i < 21632 / 4; i += 256) dst[i] = src[i];
        const float4* ws = reinterpret_cast<const float4*>(cw);
        float4* wd = reinterpret_cast<float4*>(sW);
        for (int i = threadIdx.x; i < 18432 / 4; i += 256) wd[i] = ws[i];
    }
    __syncthreads();

#pragma unroll 1
    for (int item = threadIdx.x; item < 2304; item += 256) {
        int px = item % 12;
        int py = (item / 12) % 12;
        int cg = item / 144;
        int c0 = cg * 4;

        float acc[4][4];
#pragma unroll
        for (int i = 0; i < 4; i++)
#pragma unroll
            for (int j = 0; j < 4; j++) acc[i][j] = 0.f;

        const int ib = (py * 2) * 26 + px * 2;

#pragma unroll 1
        for (int ci = 0; ci < 32; ci++) {
            const float* ip = sIn + ci * 676 + ib;
            float in[4][4];
#pragma unroll
            for (int y = 0; y < 4; y++)
#pragma unroll
                for (int xx = 0; xx < 4; xx++) in[y][xx] = ip[y * 26 + xx];

#pragma unroll
            for (int cc = 0; cc < 4; cc++) {
                const float* wp = sW + ((c0 + cc) * 32 + ci) * 9;
                float w[9];
#pragma unroll
                for (int q = 0; q < 9; q++) w[q] = wp[q];
#pragma unroll
                for (int oy = 0; oy < 2; oy++)
#pragma unroll
                    for (int ox = 0; ox < 2; ox++) {
                        float s = acc[cc][oy * 2 + ox];
#pragma unroll
                        for (int dy = 0; dy < 3; dy++)
#pragma unroll
                            for (int dx = 0; dx < 3; dx++)
                                s = fmaf(in[oy + dy][ox + dx], w[dy * 3 + dx], s);
                        acc[cc][oy * 2 + ox] = s;
                    }
            }
        }

        float* op = &g_h2[((size_t)b * 64 + c0) * 144 + py * 12 + px];
#pragma unroll
        for (int cc = 0; cc < 4; cc++) {
            float m = fmaxf(fmaxf(acc[cc][0], acc[cc][1]),
                            fmaxf(acc[cc][2], acc[cc][3]));
            op[cc * 144] = fmaxf(m + cb[c0 + cc], 0.f);
        }
    }
}

// ---------------------------------------------------------------------------
// fc1: h3[4096,128] = relu(h2[4096,9216] @ W[128,9216]^T + b)
// Tiled GEMM: BM=32, BN=128, BK=16, 4x4 register tile, 256 threads.
// ---------------------------------------------------------------------------
__global__ void k_fc1(const float* __restrict__ W,
                      const float* __restrict__ bias) {
    __shared__ float As[16][32];
    __shared__ float Bs[16][128];

    const int tid = threadIdx.x;
    const int tx = tid & 31;    // n-group (0..31), 4 outputs each
    const int ty = tid >> 5;    // m-group (0..7),  4 outputs each
    const int m0 = blockIdx.x * 32;

    const int aM = tid >> 3;          // 0..31
    const int aK = (tid & 7) * 2;     // 0,2,..,14
    const int bN = tid >> 2;          // 0..63
    const int bK = (tid & 3) * 4;     // 0,4,8,12

    const float* Ab = &g_h2[(size_t)(m0 + aM) * 9216 + aK];
    const float* B0 = W + (size_t)bN * 9216 + bK;
    const float* B1 = W + (size_t)(bN + 64) * 9216 + bK;

    float acc[4][4];
#pragma unroll
    for (int i = 0; i < 4; i++)
#pragma unroll
        for (int j = 0; j < 4; j++) acc[i][j] = 0.f;

    for (int k0 = 0; k0 < 9216; k0 += 16) {
        float2 av = *reinterpret_cast<const float2*>(Ab + k0);
        float4 b0 = *reinterpret_cast<const float4*>(B0 + k0);
        float4 b1 = *reinterpret_cast<const float4*>(B1 + k0);

        As[aK][aM]     = av.x;
        As[aK + 1][aM] = av.y;
        Bs[bK + 0][bN] = b0.x;  Bs[bK + 1][bN] = b0.y;
        Bs[bK + 2][bN] = b0.z;  Bs[bK + 3][bN] = b0.w;
        Bs[bK + 0][bN + 64] = b1.x;  Bs[bK + 1][bN + 64] = b1.y;
        Bs[bK + 2][bN + 64] = b1.z;  Bs[bK + 3][bN + 64] = b1.w;
        __syncthreads();

#pragma unroll
        for (int kk = 0; kk < 16; kk++) {
            float4 a = *reinterpret_cast<const float4*>(&As[kk][ty * 4]);
            float4 bb = *reinterpret_cast<const float4*>(&Bs[kk][tx * 4]);
            float ar[4] = {a.x, a.y, a.z, a.w};
            float br[4] = {bb.x, bb.y, bb.z, bb.w};
#pragma unroll
            for (int i = 0; i < 4; i++)
#pragma unroll
                for (int j = 0; j < 4; j++)
                    acc[i][j] = fmaf(ar[i], br[j], acc[i][j]);
        }
        __syncthreads();
    }

#pragma unroll
    for (int i = 0; i < 4; i++) {
        int m = m0 + ty * 4 + i;
#pragma unroll
        for (int j = 0; j < 4; j++) {
            int n = tx * 4 + j;
            g_h3[(size_t)m * 128 + n] = fmaxf(acc[i][j] + bias[n], 0.f);
        }
    }
}

// ---------------------------------------------------------------------------
// fc2 + GMM posterior: one thread per batch row, 128 rows per block.
// ---------------------------------------------------------------------------
__global__ void k_fc2gmm(const float* __restrict__ w2,
                         const float* __restrict__ b2,
                         const float* __restrict__ cen,
                         float* __restrict__ out) {
    extern __shared__ float sm[];
    float* sH = sm;                 // 128 * 129 (padded rows)
    float* sW = sH + 128 * 129;     // 10*128
    float* sB = sW + 1280;          // 16
    float* sC = sB + 16;            // 112 (100 used)
    float* sS = sC + 112;           // 1000
    float* sD = sS + 1000;          // 16

    const int tid = threadIdx.x;
    const int b0 = blockIdx.x * 128;

    for (int i = tid; i < 16384; i += 128)
        sH[(i >> 7) * 129 + (i & 127)] = g_h3[(size_t)b0 * 128 + i];
    for (int i = tid; i < 1280; i += 128) sW[i] = w2[i];
    for (int i = tid; i < 100; i += 128) sC[i] = cen[i];
    for (int i = tid; i < 1000; i += 128) sS[i] = g_sig[i];
    if (tid < 10) { sB[tid] = b2[tid]; sD[tid] = g_det[tid]; }
    __syncthreads();

    const float* h = sH + tid * 129;

    float y[10];
#pragma unroll
    for (int j = 0; j < 10; j++) {
        float s = sB[j];
        const float* wr = sW + j * 128;
#pragma unroll 8
        for (int k = 0; k < 128; k++) s = fmaf(h[k], wr[k], s);
        y[j] = s;
    }

    float expo[10];
    float mx = -3.4e38f;
#pragma unroll 1
    for (int k = 0; k < 10; k++) {
        float diff[10];
#pragma unroll
        for (int d = 0; d < 10; d++) diff[d] = y[d] - sC[k * 10 + d];
        float dist = 0.f;
#pragma unroll
        for (int i = 0; i < 10; i++) {
            float t = 0.f;
#pragma unroll
            for (int j = 0; j < 10; j++)
                t = fmaf(sS[k * 100 + i * 10 + j], diff[j], t);
            dist = fmaf(diff[i], t, dist);
        }
        float e = -0.5f * dist;
        expo[k] = e;
        mx = fmaxf(mx, e);
    }

    float num[10];
    float sum = 0.f;
#pragma unroll
    for (int k = 0; k < 10; k++) {
        float v = sD[k] * expf(expo[k] - mx);
        num[k] = v;
        sum += v;
    }
    float inv = 1.f / sum;

    float* op = out + (size_t)(b0 + tid) * 10;
#pragma unroll
    for (int k = 0; k < 10; k++) op[k] = num[k] * inv;
}

// ---------------------------------------------------------------------------
// kernel_launch
// ---------------------------------------------------------------------------
extern "C" void kernel_launch(void* const* d_in, const int* in_sizes, int n_in,
                              void* d_out, int out_size) {
    const float* x   = (const float*)d_in[0];
    const float* w1  = (const float*)d_in[1];
    const float* b1  = (const float*)d_in[2];
    const float* w2  = (const float*)d_in[3];
    const float* b2  = (const float*)d_in[4];
    const float* fw1 = (const float*)d_in[5];
    const float* fb1 = (const float*)d_in[6];
    const float* fw2 = (const float*)d_in[7];
    const float* fb2 = (const float*)d_in[8];
    const float* cen = (const float*)d_in[9];
    const float* raw = (const float*)d_in[10];
    float* out = (float*)d_out;

    const int SMEM_CONV2 = (21632 + 18432) * 4;                       // 160256 B
    const int SMEM_GMM   = (128 * 129 + 1280 + 16 + 112 + 1000 + 16) * 4;  // 75744 B
    cudaFuncSetAttribute(k_conv2pool, cudaFuncAttributeMaxDynamicSharedMemorySize, SMEM_CONV2);
    cudaFuncSetAttribute(k_fc2gmm,    cudaFuncAttributeMaxDynamicSharedMemorySize, SMEM_GMM);

    k_gmm_pre<<<1, 32>>>(raw);

    const int TOTAL1 = BATCH * 32 * 26 * 26;
    k_conv1<<<(TOTAL1 + 255) / 256, 256>>>(x, w1, b1);

    k_conv2pool<<<BATCH, 256, SMEM_CONV2>>>(w2, b2);

    k_fc1<<<BATCH / 32, 256>>>(fw1, fb1);

    k_fc2gmm<<<BATCH / 128, 128, SMEM_GMM>>>(fw2, fb2, cen, out);
}

// round 4
// speedup vs baseline: 1.0009x; 1.0009x over previous
#include <cuda_runtime.h>
#include <cstddef>

// ---------------------------------------------------------------------------
// Scratch (static __device__ allocations; no cudaMalloc allowed)
// ---------------------------------------------------------------------------
#define BATCH 4096

__device__ float g_h1[(size_t)BATCH * 32 * 26 * 26];   // conv1 out  (354 MB)
__device__ float g_h2[(size_t)BATCH * 64 * 12 * 12];   // conv2+pool (151 MB)
__device__ float g_h3[(size_t)BATCH * 128];            // fc1 out
__device__ float g_sig[10 * 10 * 10];                  // Sigma_inv per component
__device__ float g_det[10];                            // det_scale per component

// ---------------------------------------------------------------------------
// GMM precompute: L = tril(raw,-1)+I ; D = diag(raw)^2 + 1e-4
// Sigma_inv = L^{-T} D^{-1} L^{-1} ; det_scale = rsqrt(prod D)
// ---------------------------------------------------------------------------
__global__ void k_gmm_pre(const float* __restrict__ raw) {
    int k = threadIdx.x;
    if (k >= 10) return;
    const float* R = raw + k * 100;

    float D[10];
#pragma unroll
    for (int i = 0; i < 10; i++) {
        float r = R[i * 10 + i];
        D[i] = r * r + 1e-4f;
    }

    // Unit-lower-triangular inverse via forward substitution.
    float Li[10][10];
#pragma unroll
    for (int i = 0; i < 10; i++)
#pragma unroll
        for (int j = 0; j < 10; j++) Li[i][j] = (i == j) ? 1.f : 0.f;

    for (int j = 0; j < 10; j++) {
        for (int i = j + 1; i < 10; i++) {
            float s = 0.f;
            for (int m = j; m < i; m++) s = fmaf(R[i * 10 + m], Li[m][j], s);
            Li[i][j] = -s;
        }
    }

    for (int i = 0; i < 10; i++) {
        for (int j = 0; j < 10; j++) {
            int a0 = (i > j) ? i : j;
            float s = 0.f;
            for (int a = a0; a < 10; a++) s += Li[a][i] * Li[a][j] / D[a];
            g_sig[k * 100 + i * 10 + j] = s;
        }
    }

    float p = 1.f;
#pragma unroll
    for (int a = 0; a < 10; a++) p *= D[a];
    g_det[k] = rsqrtf(p);
}

// ---------------------------------------------------------------------------
// conv1: [B,1,28,28] -> relu -> [B,32,26,26]
// ---------------------------------------------------------------------------
__global__ void k_conv1(const float* __restrict__ x,
                        const float* __restrict__ w,
                        const float* __restrict__ bias) {
    int t = blockIdx.x * 256 + threadIdx.x;
    const int TOTAL = BATCH * 32 * 26 * 26;   // 88,604,672
    if (t >= TOTAL) return;

    int ox = t % 26;
    int r  = t / 26;
    int oy = r % 26;  r /= 26;
    int c  = r % 32;
    int b  = r / 32;

    const float* xp = x + (size_t)b * 784 + oy * 28 + ox;
    const float* wp = w + c * 9;
    float acc = bias[c];
#pragma unroll
    for (int dy = 0; dy < 3; dy++)
#pragma unroll
        for (int dx = 0; dx < 3; dx++)
            acc = fmaf(xp[dy * 28 + dx], wp[dy * 3 + dx], acc);

    g_h1[t] = fmaxf(acc, 0.f);
}

// ---------------------------------------------------------------------------
// conv2 + relu + 2x2 maxpool (fused): [B,32,26,26] -> [B,64,12,12]
// One block per image. Input image + all weights staged in smem.
// Each thread item: 4 output channels x one 2x2 pool quad (16 accumulators).
// ---------------------------------------------------------------------------
__global__ void k_conv2pool(const float* __restrict__ cw,
                            const float* __restrict__ cb) {
    const int b = blockIdx.x;
    extern __shared__ float sm[];
    float* sIn = sm;               // 32*26*26 = 21632 floats
    float* sW  = sm + 21632;       // 64*32*9  = 18432 floats

    {
        const float4* src = reinterpret_cast<const float4*>(&g_h1[(size_t)b * 21632]);
        float4* dst = reinterpret_cast<float4*>(sIn);
        for (int i = threadIdx.x; i < 21632 / 4; i += 256) dst[i] = src[i];
        const float4* ws = reinterpret_cast<const float4*>(cw);
        float4* wd = reinterpret_cast<float4*>(sW);
        for (int i = threadIdx.x; i < 18432 / 4; i += 256) wd[i] = ws[i];
    }
    __syncthreads();

#pragma unroll 1
    for (int item = threadIdx.x; item < 2304; item += 256) {
        int px = item % 12;
        int py = (item / 12) % 12;
        int cg = item / 144;
        int c0 = cg * 4;

        float acc[4][4];
#pragma unroll
        for (int i = 0; i < 4; i++)
#pragma unroll
            for (int j = 0; j < 4; j++) acc[i][j] = 0.f;

        const int ib = (py * 2) * 26 + px * 2;

#pragma unroll 1
        for (int ci = 0; ci < 32; ci++) {
            const float* ip = sIn + ci * 676 + ib;
            float in[4][4];
#pragma unroll
            for (int y = 0; y < 4; y++)
#pragma unroll
                for (int xx = 0; xx < 4; xx++) in[y][xx] = ip[y * 26 + xx];

#pragma unroll
            for (int cc = 0; cc < 4; cc++) {
                const float* wp = sW + ((c0 + cc) * 32 + ci) * 9;
                float w[9];
#pragma unroll
                for (int q = 0; q < 9; q++) w[q] = wp[q];
#pragma unroll
                for (int oy = 0; oy < 2; oy++)
#pragma unroll
                    for (int ox = 0; ox < 2; ox++) {
                        float s = acc[cc][oy * 2 + ox];
#pragma unroll
                        for (int dy = 0; dy < 3; dy++)
#pragma unroll
                            for (int dx = 0; dx < 3; dx++)
                                s = fmaf(in[oy + dy][ox + dx], w[dy * 3 + dx], s);
                        acc[cc][oy * 2 + ox] = s;
                    }
            }
        }

        float* op = &g_h2[((size_t)b * 64 + c0) * 144 + py * 12 + px];
#pragma unroll
        for (int cc = 0; cc < 4; cc++) {
            float m = fmaxf(fmaxf(acc[cc][0], acc[cc][1]),
                            fmaxf(acc[cc][2], acc[cc][3]));
            op[cc * 144] = fmaxf(m + cb[c0 + cc], 0.f);
        }
    }
}

// ---------------------------------------------------------------------------
// fc1: h3[4096,128] = relu(h2[4096,9216] @ W[128,9216]^T + b)
// Tiled GEMM: BM=32, BN=128, BK=16, 4x4 register tile, 256 threads.
// ---------------------------------------------------------------------------
__global__ void k_fc1(const float* __restrict__ W,
                      const float* __restrict__ bias) {
    __shared__ float As[16][32];
    __shared__ float Bs[16][128];

    const int tid = threadIdx.x;
    const int tx = tid & 31;    // n-group (0..31), 4 outputs each
    const int ty = tid >> 5;    // m-group (0..7),  4 outputs each
    const int m0 = blockIdx.x * 32;

    const int aM = tid >> 3;          // 0..31
    const int aK = (tid & 7) * 2;     // 0,2,..,14
    const int bN = tid >> 2;          // 0..63
    const int bK = (tid & 3) * 4;     // 0,4,8,12

    const float* Ab = &g_h2[(size_t)(m0 + aM) * 9216 + aK];
    const float* B0 = W + (size_t)bN * 9216 + bK;
    const float* B1 = W + (size_t)(bN + 64) * 9216 + bK;

    float acc[4][4];
#pragma unroll
    for (int i = 0; i < 4; i++)
#pragma unroll
        for (int j = 0; j < 4; j++) acc[i][j] = 0.f;

    for (int k0 = 0; k0 < 9216; k0 += 16) {
        float2 av = *reinterpret_cast<const float2*>(Ab + k0);
        float4 b0 = *reinterpret_cast<const float4*>(B0 + k0);
        float4 b1 = *reinterpret_cast<const float4*>(B1 + k0);

        As[aK][aM]     = av.x;
        As[aK + 1][aM] = av.y;
        Bs[bK + 0][bN] = b0.x;  Bs[bK + 1][bN] = b0.y;
        Bs[bK + 2][bN] = b0.z;  Bs[bK + 3][bN] = b0.w;
        Bs[bK + 0][bN + 64] = b1.x;  Bs[bK + 1][bN + 64] = b1.y;
        Bs[bK + 2][bN + 64] = b1.z;  Bs[bK + 3][bN + 64] = b1.w;
        __syncthreads();

#pragma unroll
        for (int kk = 0; kk < 16; kk++) {
            float4 a = *reinterpret_cast<const float4*>(&As[kk][ty * 4]);
            float4 bb = *reinterpret_cast<const float4*>(&Bs[kk][tx * 4]);
            float ar[4] = {a.x, a.y, a.z, a.w};
            float br[4] = {bb.x, bb.y, bb.z, bb.w};
#pragma unroll
            for (int i = 0; i < 4; i++)
#pragma unroll
                for (int j = 0; j < 4; j++)
                    acc[i][j] = fmaf(ar[i], br[j], acc[i][j]);
        }
        __syncthreads();
    }

#pragma unroll
    for (int i = 0; i < 4; i++) {
        int m = m0 + ty * 4 + i;
#pragma unroll
        for (int j = 0; j < 4; j++) {
            int n = tx * 4 + j;
            g_h3[(size_t)m * 128 + n] = fmaxf(acc[i][j] + bias[n], 0.f);
        }
    }
}

// ---------------------------------------------------------------------------
// fc2 + GMM posterior: one thread per batch row, 128 rows per block.
// ---------------------------------------------------------------------------
__global__ void k_fc2gmm(const float* __restrict__ w2,
                         const float* __restrict__ b2,
                         const float* __restrict__ cen,
                         float* __restrict__ out) {
    extern __shared__ float sm[];
    float* sH = sm;                 // 128 * 129 (padded rows)
    float* sW = sH + 128 * 129;     // 10*128
    float* sB = sW + 1280;          // 16
    float* sC = sB + 16;            // 112 (100 used)
    float* sS = sC + 112;           // 1000
    float* sD = sS + 1000;          // 16

    const int tid = threadIdx.x;
    const int b0 = blockIdx.x * 128;

    for (int i = tid; i < 16384; i += 128)
        sH[(i >> 7) * 129 + (i & 127)] = g_h3[(size_t)b0 * 128 + i];
    for (int i = tid; i < 1280; i += 128) sW[i] = w2[i];
    for (int i = tid; i < 100; i += 128) sC[i] = cen[i];
    for (int i = tid; i < 1000; i += 128) sS[i] = g_sig[i];
    if (tid < 10) { sB[tid] = b2[tid]; sD[tid] = g_det[tid]; }
    __syncthreads();

    const float* h = sH + tid * 129;

    float y[10];
#pragma unroll
    for (int j = 0; j < 10; j++) {
        float s = sB[j];
        const float* wr = sW + j * 128;
#pragma unroll 8
        for (int k = 0; k < 128; k++) s = fmaf(h[k], wr[k], s);
        y[j] = s;
    }

    float expo[10];
    float mx = -3.4e38f;
#pragma unroll 1
    for (int k = 0; k < 10; k++) {
        float diff[10];
#pragma unroll
        for (int d = 0; d < 10; d++) diff[d] = y[d] - sC[k * 10 + d];
        float dist = 0.f;
#pragma unroll
        for (int i = 0; i < 10; i++) {
            float t = 0.f;
#pragma unroll
            for (int j = 0; j < 10; j++)
                t = fmaf(sS[k * 100 + i * 10 + j], diff[j], t);
            dist = fmaf(diff[i], t, dist);
        }
        float e = -0.5f * dist;
        expo[k] = e;
        mx = fmaxf(mx, e);
    }

    float num[10];
    float sum = 0.f;
#pragma unroll
    for (int k = 0; k < 10; k++) {
        float v = sD[k] * expf(expo[k] - mx);
        num[k] = v;
        sum += v;
    }
    float inv = 1.f / sum;

    float* op = out + (size_t)(b0 + tid) * 10;
#pragma unroll
    for (int k = 0; k < 10; k++) op[k] = num[k] * inv;
}

// ---------------------------------------------------------------------------
// kernel_launch
// ---------------------------------------------------------------------------
extern "C" void kernel_launch(void* const* d_in, const int* in_sizes, int n_in,
                              void* d_out, int out_size) {
    const float* x   = (const float*)d_in[0];
    const float* w1  = (const float*)d_in[1];
    const float* b1  = (const float*)d_in[2];
    const float* w2  = (const float*)d_in[3];
    const float* b2  = (const float*)d_in[4];
    const float* fw1 = (const float*)d_in[5];
    const float* fb1 = (const float*)d_in[6];
    const float* fw2 = (const float*)d_in[7];
    const float* fb2 = (const float*)d_in[8];
    const float* cen = (const float*)d_in[9];
    const float* raw = (const float*)d_in[10];
    float* out = (float*)d_out;

    const int SMEM_CONV2 = (21632 + 18432) * 4;                       // 160256 B
    const int SMEM_GMM   = (128 * 129 + 1280 + 16 + 112 + 1000 + 16) * 4;  // 75744 B
    cudaFuncSetAttribute(k_conv2pool, cudaFuncAttributeMaxDynamicSharedMemorySize, SMEM_CONV2);
    cudaFuncSetAttribute(k_fc2gmm,    cudaFuncAttributeMaxDynamicSharedMemorySize, SMEM_GMM);

    k_gmm_pre<<<1, 32>>>(raw);

    const int TOTAL1 = BATCH * 32 * 26 * 26;
    k_conv1<<<(TOTAL1 + 255) / 256, 256>>>(x, w1, b1);

    k_conv2pool<<<BATCH, 256, SMEM_CONV2>>>(w2, b2);

    k_fc1<<<BATCH / 32, 256>>>(fw1, fb1);

    k_fc2gmm<<<BATCH / 128, 128, SMEM_GMM>>>(fw2, fb2, cen, out);
}

// round 5
// speedup vs baseline: 1.6187x; 1.6173x over previous
#include <cuda_runtime.h>
#include <cuda_bf16.h>
#include <cstddef>

#define BATCH 4096

// ---------------------------------------------------------------------------
// Scratch (static __device__; no cudaMalloc allowed)
// ---------------------------------------------------------------------------
__device__ float    g_h2[(size_t)BATCH * 64 * 12 * 12];   // conv2+pool out (151 MB)
__device__ float    g_h3[(size_t)BATCH * 128];            // fc1 out
__device__ float    g_sig[10 * 10 * 10];                  // Sigma_inv
__device__ float    g_det[10];                            // det_scale
__device__ unsigned g_wph[192 * 72];                      // conv2 W hi, paired bf16x2
__device__ unsigned g_wpl[192 * 72];                      // conv2 W lo, paired bf16x2

// ---------------------------------------------------------------------------
// bf16 split helpers
// ---------------------------------------------------------------------------
__device__ __forceinline__ void split_bf16(float v, unsigned& h, unsigned& l) {
    __nv_bfloat16 hb = __float2bfloat16_rn(v);
    float hf = __bfloat162float(hb);
    __nv_bfloat16 lb = __float2bfloat16_rn(v - hf);
    h = (unsigned)__bfloat16_as_ushort(hb);
    l = (unsigned)__bfloat16_as_ushort(lb);
}

#define MMA16816(Cr, Ar, b0, b1)                                              \
    asm volatile("mma.sync.aligned.m16n8k16.row.col.f32.bf16.bf16.f32 "       \
                 "{%0,%1,%2,%3}, {%4,%5,%6,%7}, {%8,%9}, {%0,%1,%2,%3};"      \
                 : "+f"(Cr[0]), "+f"(Cr[1]), "+f"(Cr[2]), "+f"(Cr[3])         \
                 : "r"(Ar[0]), "r"(Ar[1]), "r"(Ar[2]), "r"(Ar[3]),            \
                   "r"(b0), "r"(b1))

// ---------------------------------------------------------------------------
// GMM precompute (unchanged)
// ---------------------------------------------------------------------------
__global__ void k_gmm_pre(const float* __restrict__ raw) {
    int k = threadIdx.x;
    if (k >= 10) return;
    const float* R = raw + k * 100;

    float D[10];
#pragma unroll
    for (int i = 0; i < 10; i++) { float r = R[i * 10 + i]; D[i] = r * r + 1e-4f; }

    float Li[10][10];
#pragma unroll
    for (int i = 0; i < 10; i++)
#pragma unroll
        for (int j = 0; j < 10; j++) Li[i][j] = (i == j) ? 1.f : 0.f;

    for (int j = 0; j < 10; j++)
        for (int i = j + 1; i < 10; i++) {
            float s = 0.f;
            for (int m = j; m < i; m++) s = fmaf(R[i * 10 + m], Li[m][j], s);
            Li[i][j] = -s;
        }

    for (int i = 0; i < 10; i++)
        for (int j = 0; j < 10; j++) {
            int a0 = (i > j) ? i : j;
            float s = 0.f;
            for (int a = a0; a < 10; a++) s += Li[a][i] * Li[a][j] / D[a];
            g_sig[k * 100 + i * 10 + j] = s;
        }

    float p = 1.f;
#pragma unroll
    for (int a = 0; a < 10; a++) p *= D[a];
    g_det[k] = rsqrtf(p);
}

// ---------------------------------------------------------------------------
// conv2 weight prep: K layout k = ci*12 + dy*4 + dx (dx==3 -> 0 weight).
// Paired: g_wp[(k>>1)*72 + n] = bf16x2(val(k), val(k+1)), hi/lo arrays.
// ---------------------------------------------------------------------------
__global__ void k_wprep(const float* __restrict__ w2) {
    int t = blockIdx.x * 256 + threadIdx.x;
    if (t >= 192 * 72) return;
    int kp = t / 72, n = t - kp * 72;
    if (n >= 64) { g_wph[t] = 0u; g_wpl[t] = 0u; return; }

    unsigned h[2], l[2];
#pragma unroll
    for (int j = 0; j < 2; j++) {
        int k = kp * 2 + j;
        int ci = k / 12, q = k - ci * 12;
        int dy = q >> 2, dx = q & 3;
        float v = (dx < 3) ? w2[((n * 32 + ci) * 3 + dy) * 3 + dx] : 0.f;
        split_bf16(v, h[j], l[j]);
    }
    g_wph[t] = h[0] | (h[1] << 16);
    g_wpl[t] = l[0] | (l[1] << 16);
}

// ---------------------------------------------------------------------------
// Fused conv1 + conv2 + relu + maxpool, tensor cores (split-bf16 HMMA).
// One block = one image, 288 threads (9 warps). Implicit GEMM:
//   C[m=576 quad-ordered spatial][n=64 ch] = A[m][k=384] * B[k][n]
// m = quad*4 + (sy*2+sx); k = ci*12 + dy*4 + dx (dx=3 is zero weight).
// Each warp: 4 m16-strips (two groups of 2), all 8 n8-tiles, 24 k16-steps,
// 3 MMAs per step (hi*hi + hi*lo + lo*hi).
// ---------------------------------------------------------------------------
__global__ void __launch_bounds__(288, 1)
k_convfused(const float* __restrict__ x,
            const float* __restrict__ w1,
            const float* __restrict__ b1,
            const float* __restrict__ cb) {
    const int b   = blockIdx.x;
    const int tid = threadIdx.x;
    const int lane = tid & 31, wid = tid >> 5;
    const int g = lane >> 2, tg = lane & 3;

    extern __shared__ char smraw[];
    unsigned* sA  = (unsigned*)smraw;                    // [32*680] packed (hi,lo)
    unsigned* sBh = (unsigned*)(smraw + 87040);          // [192*72]
    unsigned* sBl = (unsigned*)(smraw + 142336);         // [192*72]
    float*    sX  = (float*)(smraw + 197632);            // [784]
    float*    sW1 = (float*)(smraw + 200768);            // [288]
    float*    sB1 = (float*)(smraw + 201920);            // [32]

    // Stage weights (L2-resident) + input image + conv1 params
    for (int i = tid; i < 13824; i += 288) { sBh[i] = g_wph[i]; sBl[i] = g_wpl[i]; }
    for (int i = tid; i < 784; i += 288) sX[i] = x[(size_t)b * 784 + i];
    for (int i = tid; i < 288; i += 288) sW1[i] = w1[i];
    if (tid < 32) sB1[tid] = b1[tid];
    __syncthreads();

    // conv1 -> relu -> split-bf16 packed into sA[ci*680 + y*26 + x]
    for (int idx = tid; idx < 21632; idx += 288) {
        int c = idx / 676, p = idx - c * 676;
        int y = p / 26, xx = p - y * 26;
        float acc = sB1[c];
        const float* xp = sX + y * 28 + xx;
        const float* wp = sW1 + c * 9;
#pragma unroll
        for (int dy = 0; dy < 3; dy++)
#pragma unroll
            for (int dx = 0; dx < 3; dx++)
                acc = fmaf(xp[dy * 28 + dx], wp[dy * 3 + dx], acc);
        float v = fmaxf(acc, 0.f);
        unsigned h, l; split_bf16(v, h, l);
        sA[c * 680 + p] = h | (l << 16);
    }
    // zero channel pads (read-overrun slots for dx=3, multiplied by 0 weight)
    if (tid < 128) sA[(tid >> 2) * 680 + 676 + (tid & 3)] = 0u;
    __syncthreads();

    const int kc = tg * 2;

    for (int grp = 0; grp < 2; grp++) {
        const int s0 = wid * 4 + grp * 2;   // strips s0, s0+1

        // spatial base per (strip, row-half)
        int base[2][2];
#pragma unroll
        for (int st = 0; st < 2; st++)
#pragma unroll
            for (int h = 0; h < 2; h++) {
                int m = (s0 + st) * 16 + g + h * 8;
                int quad = m >> 2, e = m & 3;
                int py = quad / 12, px = quad - py * 12;
                base[st][h] = (py * 2 + (e >> 1)) * 26 + px * 2 + (e & 1);
            }

        float C[2][8][4];
#pragma unroll
        for (int st = 0; st < 2; st++)
#pragma unroll
            for (int nt = 0; nt < 8; nt++)
#pragma unroll
                for (int q = 0; q < 4; q++) C[st][nt][q] = 0.f;

#pragma unroll 1
        for (int ks = 0; ks < 24; ks++) {
            const int k0 = ks * 16;
            int ka = k0 + kc;
            int cia = ka / 12, qa = ka - cia * 12;
            int koa = cia * 680 + (qa >> 2) * 26 + (qa & 3);
            int kb = ka + 8;
            int cib = kb / 12, qb = kb - cib * 12;
            int kob = cib * 680 + (qb >> 2) * 26 + (qb & 3);

            // B fragments for all 8 n-tiles (hi + lo)
            const unsigned* bph = sBh + ((k0 >> 1) + tg) * 72 + g;
            const unsigned* bpl = sBl + ((k0 >> 1) + tg) * 72 + g;
            unsigned B0h[8], B1h[8], B0l[8], B1l[8];
#pragma unroll
            for (int nt = 0; nt < 8; nt++) {
                B0h[nt] = bph[nt * 8];
                B1h[nt] = bph[nt * 8 + 4 * 72];
                B0l[nt] = bpl[nt * 8];
                B1l[nt] = bpl[nt * 8 + 4 * 72];
            }

#pragma unroll
            for (int st = 0; st < 2; st++) {
                unsigned ah[4], al[4];
                {
                    int i0 = base[st][0] + koa;
                    unsigned u0 = sA[i0], u1 = sA[i0 + 1];
                    ah[0] = __byte_perm(u0, u1, 0x5410);
                    al[0] = __byte_perm(u0, u1, 0x7632);
                    int i1 = base[st][1] + koa;
                    u0 = sA[i1]; u1 = sA[i1 + 1];
                    ah[1] = __byte_perm(u0, u1, 0x5410);
                    al[1] = __byte_perm(u0, u1, 0x7632);
                    int i2 = base[st][0] + kob;
                    u0 = sA[i2]; u1 = sA[i2 + 1];
                    ah[2] = __byte_perm(u0, u1, 0x5410);
                    al[2] = __byte_perm(u0, u1, 0x7632);
                    int i3 = base[st][1] + kob;
                    u0 = sA[i3]; u1 = sA[i3 + 1];
                    ah[3] = __byte_perm(u0, u1, 0x5410);
                    al[3] = __byte_perm(u0, u1, 0x7632);
                }
#pragma unroll
                for (int nt = 0; nt < 8; nt++) {
                    MMA16816(C[st][nt], ah, B0h[nt], B1h[nt]);   // hi*hi
                    MMA16816(C[st][nt], ah, B0l[nt], B1l[nt]);   // hi*lo
                    MMA16816(C[st][nt], al, B0h[nt], B1h[nt]);   // lo*hi
                }
            }
        }

        // maxpool (2 shfl.bfly over fragment rows) + bias + relu + store
#pragma unroll
        for (int st = 0; st < 2; st++) {
            const int s = s0 + st;
#pragma unroll
            for (int nt = 0; nt < 8; nt++) {
                float v0 = C[st][nt][0], v1 = C[st][nt][1];
                float v2 = C[st][nt][2], v3 = C[st][nt][3];
                v0 = fmaxf(v0, __shfl_xor_sync(0xffffffffu, v0, 4));
                v0 = fmaxf(v0, __shfl_xor_sync(0xffffffffu, v0, 8));
                v1 = fmaxf(v1, __shfl_xor_sync(0xffffffffu, v1, 4));
                v1 = fmaxf(v1, __shfl_xor_sync(0xffffffffu, v1, 8));
                v2 = fmaxf(v2, __shfl_xor_sync(0xffffffffu, v2, 4));
                v2 = fmaxf(v2, __shfl_xor_sync(0xffffffffu, v2, 8));
                v3 = fmaxf(v3, __shfl_xor_sync(0xffffffffu, v3, 4));
                v3 = fmaxf(v3, __shfl_xor_sync(0xffffffffu, v3, 8));
                if ((lane & 12) == 0) {
                    int a  = lane >> 4;
                    int qA = s * 4 + a, qB = qA + 2;
                    int n  = nt * 8 + tg * 2;
                    float bn0 = __ldg(cb + n), bn1 = __ldg(cb + n + 1);
                    float* o = g_h2 + ((size_t)b * 64 + n) * 144;
                    o[qA]       = fmaxf(v0 + bn0, 0.f);
                    o[144 + qA] = fmaxf(v1 + bn1, 0.f);
                    o[qB]       = fmaxf(v2 + bn0, 0.f);
                    o[144 + qB] = fmaxf(v3 + bn1, 0.f);
                }
            }
        }
    }
}

// ---------------------------------------------------------------------------
// fc1: relu(h2[4096,9216] @ W[128,9216]^T + b). BM=16, BN=128, BK=32,
// 256 blocks (was 128 -> grid-starved), 256 threads, 2x4 per thread.
// ---------------------------------------------------------------------------
__global__ void k_fc1(const float* __restrict__ W,
                      const float* __restrict__ bias) {
    __shared__ float As[32][18];
    __shared__ float Bs[32][132];

    const int tid = threadIdx.x;
    const int tx = tid & 31, ty = tid >> 5;
    const int m0 = blockIdx.x * 16;

    const int ar = tid >> 4;            // 0..15
    const int ak = (tid & 15) * 2;      // 0..30
    const int bn = tid >> 1;            // 0..127
    const int bk = (tid & 1) * 16;      // 0 or 16

    const float* Ap = g_h2 + (size_t)(m0 + ar) * 9216 + ak;
    const float* Bp = W + (size_t)bn * 9216 + bk;

    float acc[2][4];
#pragma unroll
    for (int i = 0; i < 2; i++)
#pragma unroll
        for (int j = 0; j < 4; j++) acc[i][j] = 0.f;

    for (int k0 = 0; k0 < 9216; k0 += 32) {
        float2 av = *reinterpret_cast<const float2*>(Ap + k0);
        float4 q0 = *reinterpret_cast<const float4*>(Bp + k0);
        float4 q1 = *reinterpret_cast<const float4*>(Bp + k0 + 4);
        float4 q2 = *reinterpret_cast<const float4*>(Bp + k0 + 8);
        float4 q3 = *reinterpret_cast<const float4*>(Bp + k0 + 12);

        As[ak][ar] = av.x; As[ak + 1][ar] = av.y;
        Bs[bk + 0][bn] = q0.x;  Bs[bk + 1][bn] = q0.y;
        Bs[bk + 2][bn] = q0.z;  Bs[bk + 3][bn] = q0.w;
        Bs[bk + 4][bn] = q1.x;  Bs[bk + 5][bn] = q1.y;
        Bs[bk + 6][bn] = q1.z;  Bs[bk + 7][bn] = q1.w;
        Bs[bk + 8][bn] = q2.x;  Bs[bk + 9][bn] = q2.y;
        Bs[bk + 10][bn] = q2.z; Bs[bk + 11][bn] = q2.w;
        Bs[bk + 12][bn] = q3.x; Bs[bk + 13][bn] = q3.y;
        Bs[bk + 14][bn] = q3.z; Bs[bk + 15][bn] = q3.w;
        __syncthreads();

#pragma unroll
        for (int kk = 0; kk < 32; kk++) {
            float2 a = *reinterpret_cast<const float2*>(&As[kk][ty * 2]);
            float4 bb = *reinterpret_cast<const float4*>(&Bs[kk][tx * 4]);
            acc[0][0] = fmaf(a.x, bb.x, acc[0][0]);
            acc[0][1] = fmaf(a.x, bb.y, acc[0][1]);
            acc[0][2] = fmaf(a.x, bb.z, acc[0][2]);
            acc[0][3] = fmaf(a.x, bb.w, acc[0][3]);
            acc[1][0] = fmaf(a.y, bb.x, acc[1][0]);
            acc[1][1] = fmaf(a.y, bb.y, acc[1][1]);
            acc[1][2] = fmaf(a.y, bb.z, acc[1][2]);
            acc[1][3] = fmaf(a.y, bb.w, acc[1][3]);
        }
        __syncthreads();
    }

#pragma unroll
    for (int i = 0; i < 2; i++) {
        int m = m0 + ty * 2 + i;
#pragma unroll
        for (int j = 0; j < 4; j++) {
            int n = tx * 4 + j;
            g_h3[(size_t)m * 128 + n] = fmaxf(acc[i][j] + bias[n], 0.f);
        }
    }
}

// ---------------------------------------------------------------------------
// fc2 + GMM posterior (unchanged, passing)
// ---------------------------------------------------------------------------
__global__ void k_fc2gmm(const float* __restrict__ w2,
                         const float* __restrict__ b2,
                         const float* __restrict__ cen,
                         float* __restrict__ out) {
    extern __shared__ float sm[];
    float* sH = sm;
    float* sW = sH + 128 * 129;
    float* sB = sW + 1280;
    float* sC = sB + 16;
    float* sS = sC + 112;
    float* sD = sS + 1000;

    const int tid = threadIdx.x;
    const int b0 = blockIdx.x * 128;

    for (int i = tid; i < 16384; i += 128)
        sH[(i >> 7) * 129 + (i & 127)] = g_h3[(size_t)b0 * 128 + i];
    for (int i = tid; i < 1280; i += 128) sW[i] = w2[i];
    for (int i = tid; i < 100; i += 128) sC[i] = cen[i];
    for (int i = tid; i < 1000; i += 128) sS[i] = g_sig[i];
    if (tid < 10) { sB[tid] = b2[tid]; sD[tid] = g_det[tid]; }
    __syncthreads();

    const float* h = sH + tid * 129;

    float y[10];
#pragma unroll
    for (int j = 0; j < 10; j++) {
        float s = sB[j];
        const float* wr = sW + j * 128;
#pragma unroll 8
        for (int k = 0; k < 128; k++) s = fmaf(h[k], wr[k], s);
        y[j] = s;
    }

    float expo[10];
    float mx = -3.4e38f;
#pragma unroll 1
    for (int k = 0; k < 10; k++) {
        float diff[10];
#pragma unroll
        for (int d = 0; d < 10; d++) diff[d] = y[d] - sC[k * 10 + d];
        float dist = 0.f;
#pragma unroll
        for (int i = 0; i < 10; i++) {
            float t = 0.f;
#pragma unroll
            for (int j = 0; j < 10; j++)
                t = fmaf(sS[k * 100 + i * 10 + j], diff[j], t);
            dist = fmaf(diff[i], t, dist);
        }
        float e = -0.5f * dist;
        expo[k] = e;
        mx = fmaxf(mx, e);
    }

    float num[10];
    float sum = 0.f;
#pragma unroll
    for (int k = 0; k < 10; k++) {
        float v = sD[k] * expf(expo[k] - mx);
        num[k] = v;
        sum += v;
    }
    float inv = 1.f / sum;

    float* op = out + (size_t)(b0 + tid) * 10;
#pragma unroll
    for (int k = 0; k < 10; k++) op[k] = num[k] * inv;
}

// ---------------------------------------------------------------------------
// kernel_launch
// ---------------------------------------------------------------------------
extern "C" void kernel_launch(void* const* d_in, const int* in_sizes, int n_in,
                              void* d_out, int out_size) {
    const float* x   = (const float*)d_in[0];
    const float* w1  = (const float*)d_in[1];
    const float* b1  = (const float*)d_in[2];
    const float* w2  = (const float*)d_in[3];
    const float* b2  = (const float*)d_in[4];
    const float* fw1 = (const float*)d_in[5];
    const float* fb1 = (const float*)d_in[6];
    const float* fw2 = (const float*)d_in[7];
    const float* fb2 = (const float*)d_in[8];
    const float* cen = (const float*)d_in[9];
    const float* raw = (const float*)d_in[10];
    float* out = (float*)d_out;

    const int SMEM_CONV = 202048;
    const int SMEM_GMM  = (128 * 129 + 1280 + 16 + 112 + 1000 + 16) * 4;
    cudaFuncSetAttribute(k_convfused, cudaFuncAttributeMaxDynamicSharedMemorySize, SMEM_CONV);
    cudaFuncSetAttribute(k_fc2gmm,    cudaFuncAttributeMaxDynamicSharedMemorySize, SMEM_GMM);

    k_gmm_pre<<<1, 32>>>(raw);
    k_wprep<<<(192 * 72 + 255) / 256, 256>>>(w2);
    k_convfused<<<BATCH, 288, SMEM_CONV>>>(x, w1, b1, b2);
    k_fc1<<<BATCH / 16, 256>>>(fw1, fb1);
    k_fc2gmm<<<BATCH / 128, 128, SMEM_GMM>>>(fw2, fb2, cen, out);
}

// round 6
// speedup vs baseline: 2.1460x; 1.3257x over previous
#include <cuda_runtime.h>
#include <cuda_bf16.h>
#include <cstddef>

#define BATCH 4096

// ---------------------------------------------------------------------------
// Scratch (static __device__; no cudaMalloc allowed)
// ---------------------------------------------------------------------------
__device__ unsigned g_h2[(size_t)BATCH * 9216];   // conv2+pool out, packed (hi|lo<<16) split-bf16
__device__ float    g_h3[(size_t)BATCH * 128];    // fc1 out
__device__ float    g_sig[10 * 10 * 10];          // Sigma_inv
__device__ float    g_det[10];                    // det_scale
__device__ unsigned g_wph[144 * 72];              // conv2 W hi, paired bf16x2, k=(dy*3+dx)*32+ci
__device__ unsigned g_wpl[144 * 72];              // conv2 W lo
__device__ unsigned g_f1h[4608 * 128];            // fc1 W hi, paired bf16x2 [k/2][n]
__device__ unsigned g_f1l[4608 * 128];            // fc1 W lo

// ---------------------------------------------------------------------------
// helpers
// ---------------------------------------------------------------------------
__device__ __forceinline__ void split_bf16(float v, unsigned& h, unsigned& l) {
    __nv_bfloat16 hb = __float2bfloat16_rn(v);
    float hf = __bfloat162float(hb);
    __nv_bfloat16 lb = __float2bfloat16_rn(v - hf);
    h = (unsigned)__bfloat16_as_ushort(hb);
    l = (unsigned)__bfloat16_as_ushort(lb);
}

#define MMA16816(Cr, Ar, b0, b1)                                              \
    asm volatile("mma.sync.aligned.m16n8k16.row.col.f32.bf16.bf16.f32 "       \
                 "{%0,%1,%2,%3}, {%4,%5,%6,%7}, {%8,%9}, {%0,%1,%2,%3};"      \
                 : "+f"(Cr[0]), "+f"(Cr[1]), "+f"(Cr[2]), "+f"(Cr[3])         \
                 : "r"(Ar[0]), "r"(Ar[1]), "r"(Ar[2]), "r"(Ar[3]),            \
                   "r"(b0), "r"(b1))

// ---------------------------------------------------------------------------
// GMM precompute (unchanged)
// ---------------------------------------------------------------------------
__global__ void k_gmm_pre(const float* __restrict__ raw) {
    int k = threadIdx.x;
    if (k >= 10) return;
    const float* R = raw + k * 100;

    float D[10];
#pragma unroll
    for (int i = 0; i < 10; i++) { float r = R[i * 10 + i]; D[i] = r * r + 1e-4f; }

    float Li[10][10];
#pragma unroll
    for (int i = 0; i < 10; i++)
#pragma unroll
        for (int j = 0; j < 10; j++) Li[i][j] = (i == j) ? 1.f : 0.f;

    for (int j = 0; j < 10; j++)
        for (int i = j + 1; i < 10; i++) {
            float s = 0.f;
            for (int m = j; m < i; m++) s = fmaf(R[i * 10 + m], Li[m][j], s);
            Li[i][j] = -s;
        }

    for (int i = 0; i < 10; i++)
        for (int j = 0; j < 10; j++) {
            int a0 = (i > j) ? i : j;
            float s = 0.f;
            for (int a = a0; a < 10; a++) s += Li[a][i] * Li[a][j] / D[a];
            g_sig[k * 100 + i * 10 + j] = s;
        }

    float p = 1.f;
#pragma unroll
    for (int a = 0; a < 10; a++) p *= D[a];
    g_det[k] = rsqrtf(p);
}

// ---------------------------------------------------------------------------
// conv2 weight prep. K layout: k = (dy*3+dx)*32 + ci, K=288 (no padding).
// g_wp[kp*72 + n] = bf16x2( val(2kp), val(2kp+1) ): pairs are ci-adjacent.
// ---------------------------------------------------------------------------
__global__ void k_wprep(const float* __restrict__ w2) {
    int t = blockIdx.x * 256 + threadIdx.x;
    if (t >= 144 * 72) return;
    int kp = t / 72, n = t - kp * 72;
    if (n >= 64) { g_wph[t] = 0u; g_wpl[t] = 0u; return; }

    int w  = kp >> 4;             // window pos 0..8
    int ci = (kp & 15) * 2;       // channel pair
    int dy = w / 3, dx = w - dy * 3;

    unsigned h[2], l[2];
#pragma unroll
    for (int j = 0; j < 2; j++) {
        float v = w2[((n * 32 + ci + j) * 3 + dy) * 3 + dx];
        split_bf16(v, h[j], l[j]);
    }
    g_wph[t] = h[0] | (h[1] << 16);
    g_wpl[t] = l[0] | (l[1] << 16);
}

// ---------------------------------------------------------------------------
// fc1 weight prep: g_f1{h,l}[kp*128+n] = bf16x2(W[n][2kp], W[n][2kp+1]).
// Tiled smem transpose: both gmem sides coalesced.
// ---------------------------------------------------------------------------
__global__ void k_f1prep(const float* __restrict__ W) {
    __shared__ unsigned sh[32][132], sl[32][132];
    const int kp0 = blockIdx.x * 32;      // 144 blocks
    const int t = threadIdx.x;            // 256
    const int n = t >> 1, half = t & 1;

    const float* src = W + (size_t)n * 9216 + kp0 * 2 + half * 32;
#pragma unroll
    for (int j = 0; j < 16; j++) {
        float v0 = src[2 * j], v1 = src[2 * j + 1];
        unsigned h0, l0, h1, l1;
        split_bf16(v0, h0, l0);
        split_bf16(v1, h1, l1);
        sh[half * 16 + j][n] = h0 | (h1 << 16);
        sl[half * 16 + j][n] = l0 | (l1 << 16);
    }
    __syncthreads();

    const int kpl = t >> 3, c0 = (t & 7) * 16;
    unsigned* dh = &g_f1h[(size_t)(kp0 + kpl) * 128 + c0];
    unsigned* dl = &g_f1l[(size_t)(kp0 + kpl) * 128 + c0];
#pragma unroll
    for (int j = 0; j < 4; j++) {
        ((uint4*)dh)[j] = ((uint4*)&sh[kpl][c0])[j];
        ((uint4*)dl)[j] = ((uint4*)&sl[kpl][c0])[j];
    }
}

// ---------------------------------------------------------------------------
// Fused conv1 + conv2 + relu + maxpool, split-bf16 HMMA, channel-minor K.
// One block = one image, 288 threads (9 warps).
//   C[m=576 quad-ordered][n=64] = A[m][k=288] * B[k][n],  k=(dy*3+dx)*32+ci
// conv1 output stored channel-interleaved: sA{h,l}[p][ci] u16, row pad 34.
// Each warp: 4 m16-strips, 8 n8-tiles, 18 k16-steps, 3 MMAs each (split).
// ---------------------------------------------------------------------------
__global__ void __launch_bounds__(288, 1)
k_convfused(const float* __restrict__ x,
            const float* __restrict__ w1,
            const float* __restrict__ b1,
            const float* __restrict__ cb) {
    const int b   = blockIdx.x;
    const int tid = threadIdx.x;
    const int lane = tid & 31, wid = tid >> 5;
    const int g = lane >> 2, tg = lane & 3;

    extern __shared__ char smraw[];
    unsigned short* sAh = (unsigned short*)smraw;               // [676][34] u16
    unsigned short* sAl = (unsigned short*)(smraw + 46080);
    unsigned* sBh = (unsigned*)(smraw + 92160);                 // [144*72]
    unsigned* sBl = (unsigned*)(smraw + 133632);
    float*    sX  = (float*)(smraw + 175104);                   // [784]
    float*    sW1 = (float*)(smraw + 178240);                   // [288]
    float*    sB1 = (float*)(smraw + 179392);                   // [32]
    const unsigned* sA32h = (const unsigned*)sAh;
    const unsigned* sA32l = (const unsigned*)sAl;

    for (int i = tid; i < 10368; i += 288) { sBh[i] = g_wph[i]; sBl[i] = g_wpl[i]; }
    for (int i = tid; i < 784; i += 288) sX[i] = x[(size_t)b * 784 + i];
    if (tid < 288) sW1[tid] = w1[tid];
    if (tid < 32) sB1[tid] = b1[tid];
    __syncthreads();

    // conv1 -> relu -> split, channel-interleaved
    for (int idx = tid; idx < 21632; idx += 288) {
        int c = idx / 676, p = idx - c * 676;
        int y = p / 26, xx = p - y * 26;
        float acc = sB1[c];
        const float* xp = sX + y * 28 + xx;
        const float* wp = sW1 + c * 9;
#pragma unroll
        for (int dy = 0; dy < 3; dy++)
#pragma unroll
            for (int dx = 0; dx < 3; dx++)
                acc = fmaf(xp[dy * 28 + dx], wp[dy * 3 + dx], acc);
        float v = fmaxf(acc, 0.f);
        unsigned h, l; split_bf16(v, h, l);
        sAh[p * 34 + c] = (unsigned short)h;
        sAl[p * 34 + c] = (unsigned short)l;
    }
    __syncthreads();

    // spatial base per (strip, row-half): m = (wid*4+st)*16 + g + h*8
    int base[4][2];
#pragma unroll
    for (int st = 0; st < 4; st++)
#pragma unroll
        for (int h = 0; h < 2; h++) {
            int m = (wid * 4 + st) * 16 + g + h * 8;
            int quad = m >> 2, e = m & 3;
            int py = quad / 12, px = quad - py * 12;
            base[st][h] = (py * 2 + (e >> 1)) * 26 + px * 2 + (e & 1);
        }

    float C[4][8][4];
#pragma unroll
    for (int st = 0; st < 4; st++)
#pragma unroll
        for (int nt = 0; nt < 8; nt++)
#pragma unroll
            for (int q = 0; q < 4; q++) C[st][nt][q] = 0.f;

#pragma unroll 1
    for (int ks = 0; ks < 18; ks++) {
        const int w = ks >> 1;
        const int dy = w / 3;
        const int off = dy * 26 + (w - dy * 3);          // spatial offset
        const int cA = (ks & 1) * 8 + tg;                // u32 col in 17-wide A rows

        // B fragments once per ks (shared by all 4 strips)
        const unsigned* bph = sBh + (ks * 8 + tg) * 72 + g;
        const unsigned* bpl = sBl + (ks * 8 + tg) * 72 + g;
        unsigned B0h[8], B1h[8], B0l[8], B1l[8];
#pragma unroll
        for (int nt = 0; nt < 8; nt++) {
            B0h[nt] = bph[nt * 8];
            B1h[nt] = bph[nt * 8 + 4 * 72];
            B0l[nt] = bpl[nt * 8];
            B1l[nt] = bpl[nt * 8 + 4 * 72];
        }

#pragma unroll
        for (int st = 0; st < 4; st++) {
            const int r0 = (base[st][0] + off) * 17 + cA;
            const int r1 = (base[st][1] + off) * 17 + cA;
            unsigned ah[4], al[4];
            ah[0] = sA32h[r0];     al[0] = sA32l[r0];
            ah[1] = sA32h[r1];     al[1] = sA32l[r1];
            ah[2] = sA32h[r0 + 4]; al[2] = sA32l[r0 + 4];
            ah[3] = sA32h[r1 + 4]; al[3] = sA32l[r1 + 4];
#pragma unroll
            for (int nt = 0; nt < 8; nt++) {
                MMA16816(C[st][nt], ah, B0h[nt], B1h[nt]);   // hi*hi
                MMA16816(C[st][nt], ah, B0l[nt], B1l[nt]);   // hi*lo
                MMA16816(C[st][nt], al, B0h[nt], B1h[nt]);   // lo*hi
            }
        }
    }

    // maxpool via shfl + bias + relu + split-pack store
#pragma unroll
    for (int st = 0; st < 4; st++) {
        const int s = wid * 4 + st;
#pragma unroll
        for (int nt = 0; nt < 8; nt++) {
            float v0 = C[st][nt][0], v1 = C[st][nt][1];
            float v2 = C[st][nt][2], v3 = C[st][nt][3];
            v0 = fmaxf(v0, __shfl_xor_sync(0xffffffffu, v0, 4));
            v0 = fmaxf(v0, __shfl_xor_sync(0xffffffffu, v0, 8));
            v1 = fmaxf(v1, __shfl_xor_sync(0xffffffffu, v1, 4));
            v1 = fmaxf(v1, __shfl_xor_sync(0xffffffffu, v1, 8));
            v2 = fmaxf(v2, __shfl_xor_sync(0xffffffffu, v2, 4));
            v2 = fmaxf(v2, __shfl_xor_sync(0xffffffffu, v2, 8));
            v3 = fmaxf(v3, __shfl_xor_sync(0xffffffffu, v3, 4));
            v3 = fmaxf(v3, __shfl_xor_sync(0xffffffffu, v3, 8));
            if ((lane & 12) == 0) {
                int a  = lane >> 4;
                int qA = s * 4 + a, qB = qA + 2;
                int n  = nt * 8 + tg * 2;
                float bn0 = __ldg(cb + n), bn1 = __ldg(cb + n + 1);
                unsigned* o = g_h2 + ((size_t)b * 64 + n) * 144;
                unsigned hh, ll;
                split_bf16(fmaxf(v0 + bn0, 0.f), hh, ll); o[qA]       = hh | (ll << 16);
                split_bf16(fmaxf(v1 + bn1, 0.f), hh, ll); o[144 + qA] = hh | (ll << 16);
                split_bf16(fmaxf(v2 + bn0, 0.f), hh, ll); o[qB]       = hh | (ll << 16);
                split_bf16(fmaxf(v3 + bn1, 0.f), hh, ll); o[144 + qB] = hh | (ll << 16);
            }
        }
    }
}

// ---------------------------------------------------------------------------
// fc1 on tensor cores: relu(h2[4096,9216] @ W[128,9216]^T + b).
// BM=32, BN=128, BK=64; 128 blocks x 256 thr (8 warps, 2(M)x4(N)),
// warp tile m16n32; split-bf16 (3 MMAs); register-prefetched staging.
// ---------------------------------------------------------------------------
__global__ void __launch_bounds__(256)
k_fc1(const float* __restrict__ bias) {
    __shared__ unsigned As[32][68];    // [m][k] packed u32 elems
    __shared__ unsigned Bh[32][136];   // [kp][n]
    __shared__ unsigned Bl[32][136];

    const int tid = threadIdx.x;
    const int lane = tid & 31, warp = tid >> 5;
    const int g = lane >> 2, tg = lane & 3;
    const int mw = warp >> 2, nw = warp & 3;
    const int m0 = blockIdx.x * 32;

    const int ar = tid >> 3, ac = (tid & 7) * 8;
    const int br = tid >> 3, bc = (tid & 7) * 16;

    const unsigned* Ap = g_h2 + (size_t)(m0 + ar) * 9216 + ac;
    const unsigned* Bph = g_f1h + (size_t)br * 128 + bc;
    const unsigned* Bpl = g_f1l + (size_t)br * 128 + bc;

    float C[4][4];
#pragma unroll
    for (int i = 0; i < 4; i++)
#pragma unroll
        for (int j = 0; j < 4; j++) C[i][j] = 0.f;

    uint4 avr[2], bhr[4], blr[4];
    // prefetch iter 0
#pragma unroll
    for (int j = 0; j < 2; j++) avr[j] = ((const uint4*)Ap)[j];
#pragma unroll
    for (int j = 0; j < 4; j++) {
        bhr[j] = ((const uint4*)Bph)[j];
        blr[j] = ((const uint4*)Bpl)[j];
    }

#pragma unroll 1
    for (int it = 0; it < 144; it++) {
        __syncthreads();
#pragma unroll
        for (int j = 0; j < 2; j++) ((uint4*)&As[ar][ac])[j] = avr[j];
#pragma unroll
        for (int j = 0; j < 4; j++) {
            ((uint4*)&Bh[br][bc])[j] = bhr[j];
            ((uint4*)&Bl[br][bc])[j] = blr[j];
        }
        __syncthreads();

        if (it + 1 < 144) {
            const unsigned* ap = Ap + (it + 1) * 64;
            const unsigned* bp = Bph + (size_t)(it + 1) * 32 * 128;
            const unsigned* lp = Bpl + (size_t)(it + 1) * 32 * 128;
#pragma unroll
            for (int j = 0; j < 2; j++) avr[j] = ((const uint4*)ap)[j];
#pragma unroll
            for (int j = 0; j < 4; j++) {
                bhr[j] = ((const uint4*)bp)[j];
                blr[j] = ((const uint4*)lp)[j];
            }
        }

#pragma unroll
        for (int ks = 0; ks < 4; ks++) {
            const int kc = ks * 16 + 2 * tg;
            const int r0 = mw * 16 + g, r1 = r0 + 8;
            unsigned ah[4], al[4];
            {
                uint2 u = *(const uint2*)&As[r0][kc];
                ah[0] = __byte_perm(u.x, u.y, 0x5410);
                al[0] = __byte_perm(u.x, u.y, 0x7632);
                uint2 v = *(const uint2*)&As[r1][kc];
                ah[1] = __byte_perm(v.x, v.y, 0x5410);
                al[1] = __byte_perm(v.x, v.y, 0x7632);
                uint2 w = *(const uint2*)&As[r0][kc + 8];
                ah[2] = __byte_perm(w.x, w.y, 0x5410);
                al[2] = __byte_perm(w.x, w.y, 0x7632);
                uint2 z = *(const uint2*)&As[r1][kc + 8];
                ah[3] = __byte_perm(z.x, z.y, 0x5410);
                al[3] = __byte_perm(z.x, z.y, 0x7632);
            }
            const int kp = ks * 8 + tg;
#pragma unroll
            for (int nt = 0; nt < 4; nt++) {
                const int n = nw * 32 + nt * 8 + g;
                unsigned b0h = Bh[kp][n],     b1h = Bh[kp + 4][n];
                unsigned b0l = Bl[kp][n],     b1l = Bl[kp + 4][n];
                MMA16816(C[nt], ah, b0h, b1h);
                MMA16816(C[nt], ah, b0l, b1l);
                MMA16816(C[nt], al, b0h, b1h);
            }
        }
    }

    const int m = m0 + mw * 16 + g;
#pragma unroll
    for (int nt = 0; nt < 4; nt++) {
        const int n = nw * 32 + nt * 8 + 2 * tg;
        float b0 = bias[n], b1 = bias[n + 1];
        g_h3[(size_t)m * 128 + n]           = fmaxf(C[nt][0] + b0, 0.f);
        g_h3[(size_t)m * 128 + n + 1]       = fmaxf(C[nt][1] + b1, 0.f);
        g_h3[(size_t)(m + 8) * 128 + n]     = fmaxf(C[nt][2] + b0, 0.f);
        g_h3[(size_t)(m + 8) * 128 + n + 1] = fmaxf(C[nt][3] + b1, 0.f);
    }
}

// ---------------------------------------------------------------------------
// fc2 + GMM posterior (unchanged, passing)
// ---------------------------------------------------------------------------
__global__ void k_fc2gmm(const float* __restrict__ w2,
                         const float* __restrict__ b2,
                         const float* __restrict__ cen,
                         float* __restrict__ out) {
    extern __shared__ float sm[];
    float* sH = sm;
    float* sW = sH + 128 * 129;
    float* sB = sW + 1280;
    float* sC = sB + 16;
    float* sS = sC + 112;
    float* sD = sS + 1000;

    const int tid = threadIdx.x;
    const int b0 = blockIdx.x * 128;

    for (int i = tid; i < 16384; i += 128)
        sH[(i >> 7) * 129 + (i & 127)] = g_h3[(size_t)b0 * 128 + i];
    for (int i = tid; i < 1280; i += 128) sW[i] = w2[i];
    for (int i = tid; i < 100; i += 128) sC[i] = cen[i];
    for (int i = tid; i < 1000; i += 128) sS[i] = g_sig[i];
    if (tid < 10) { sB[tid] = b2[tid]; sD[tid] = g_det[tid]; }
    __syncthreads();

    const float* h = sH + tid * 129;

    float y[10];
#pragma unroll
    for (int j = 0; j < 10; j++) {
        float s = sB[j];
        const float* wr = sW + j * 128;
#pragma unroll 8
        for (int k = 0; k < 128; k++) s = fmaf(h[k], wr[k], s);
        y[j] = s;
    }

    float expo[10];
    float mx = -3.4e38f;
#pragma unroll 1
    for (int k = 0; k < 10; k++) {
        float diff[10];
#pragma unroll
        for (int d = 0; d < 10; d++) diff[d] = y[d] - sC[k * 10 + d];
        float dist = 0.f;
#pragma unroll
        for (int i = 0; i < 10; i++) {
            float t = 0.f;
#pragma unroll
            for (int j = 0; j < 10; j++)
                t = fmaf(sS[k * 100 + i * 10 + j], diff[j], t);
            dist = fmaf(diff[i], t, dist);
        }
        float e = -0.5f * dist;
        expo[k] = e;
        mx = fmaxf(mx, e);
    }

    float num[10];
    float sum = 0.f;
#pragma unroll
    for (int k = 0; k < 10; k++) {
        float v = sD[k] * expf(expo[k] - mx);
        num[k] = v;
        sum += v;
    }
    float inv = 1.f / sum;

    float* op = out + (size_t)(b0 + tid) * 10;
#pragma unroll
    for (int k = 0; k < 10; k++) op[k] = num[k] * inv;
}

// ---------------------------------------------------------------------------
// kernel_launch
// ---------------------------------------------------------------------------
extern "C" void kernel_launch(void* const* d_in, const int* in_sizes, int n_in,
                              void* d_out, int out_size) {
    const float* x   = (const float*)d_in[0];
    const float* w1  = (const float*)d_in[1];
    const float* b1  = (const float*)d_in[2];
    const float* w2  = (const float*)d_in[3];
    const float* b2  = (const float*)d_in[4];
    const float* fw1 = (const float*)d_in[5];
    const float* fb1 = (const float*)d_in[6];
    const float* fw2 = (const float*)d_in[7];
    const float* fb2 = (const float*)d_in[8];
    const float* cen = (const float*)d_in[9];
    const float* raw = (const float*)d_in[10];
    float* out = (float*)d_out;

    const int SMEM_CONV = 179520;
    const int SMEM_GMM  = (128 * 129 + 1280 + 16 + 112 + 1000 + 16) * 4;
    cudaFuncSetAttribute(k_convfused, cudaFuncAttributeMaxDynamicSharedMemorySize, SMEM_CONV);
    cudaFuncSetAttribute(k_fc2gmm,    cudaFuncAttributeMaxDynamicSharedMemorySize, SMEM_GMM);

    k_gmm_pre<<<1, 32>>>(raw);
    k_wprep<<<(144 * 72 + 255) / 256, 256>>>(w2);
    k_f1prep<<<144, 256>>>(fw1);
    k_convfused<<<BATCH, 288, SMEM_CONV>>>(x, w1, b1, b2);
    k_fc1<<<BATCH / 32, 256>>>(fb1);
    k_fc2gmm<<<BATCH / 128, 128, SMEM_GMM>>>(fw2, fb2, cen, out);
}

// round 7
// speedup vs baseline: 2.2589x; 1.0526x over previous
#include <cuda_runtime.h>
#include <cuda_bf16.h>
#include <cstddef>

#define BATCH 4096

// ---------------------------------------------------------------------------
// Scratch (static __device__; no cudaMalloc allowed)
// ---------------------------------------------------------------------------
__device__ unsigned g_h2[(size_t)BATCH * 9216];   // conv2+pool out, packed (hi|lo<<16) split-bf16
__device__ float    g_h3[(size_t)BATCH * 128];    // fc1 out
__device__ float    g_sig[10 * 10 * 10];          // Sigma_inv
__device__ float    g_det[10];                    // det_scale
__device__ unsigned g_wph[144 * 72];              // conv2 W hi, paired bf16x2, k=(dy*3+dx)*32+ci
__device__ unsigned g_wpl[144 * 72];              // conv2 W lo
__device__ unsigned g_f1h[4608 * 128];            // fc1 W hi, paired bf16x2 [k/2][n]
__device__ unsigned g_f1l[4608 * 128];            // fc1 W lo

// ---------------------------------------------------------------------------
// helpers
// ---------------------------------------------------------------------------
__device__ __forceinline__ void split_bf16(float v, unsigned& h, unsigned& l) {
    __nv_bfloat16 hb = __float2bfloat16_rn(v);
    float hf = __bfloat162float(hb);
    __nv_bfloat16 lb = __float2bfloat16_rn(v - hf);
    h = (unsigned)__bfloat16_as_ushort(hb);
    l = (unsigned)__bfloat16_as_ushort(lb);
}

#define MMA16816(Cr, Ar, b0, b1)                                              \
    asm volatile("mma.sync.aligned.m16n8k16.row.col.f32.bf16.bf16.f32 "       \
                 "{%0,%1,%2,%3}, {%4,%5,%6,%7}, {%8,%9}, {%0,%1,%2,%3};"      \
                 : "+f"(Cr[0]), "+f"(Cr[1]), "+f"(Cr[2]), "+f"(Cr[3])         \
                 : "r"(Ar[0]), "r"(Ar[1]), "r"(Ar[2]), "r"(Ar[3]),            \
                   "r"(b0), "r"(b1))

// ---------------------------------------------------------------------------
// GMM precompute (unchanged)
// ---------------------------------------------------------------------------
__global__ void k_gmm_pre(const float* __restrict__ raw) {
    int k = threadIdx.x;
    if (k >= 10) return;
    const float* R = raw + k * 100;

    float D[10];
#pragma unroll
    for (int i = 0; i < 10; i++) { float r = R[i * 10 + i]; D[i] = r * r + 1e-4f; }

    float Li[10][10];
#pragma unroll
    for (int i = 0; i < 10; i++)
#pragma unroll
        for (int j = 0; j < 10; j++) Li[i][j] = (i == j) ? 1.f : 0.f;

    for (int j = 0; j < 10; j++)
        for (int i = j + 1; i < 10; i++) {
            float s = 0.f;
            for (int m = j; m < i; m++) s = fmaf(R[i * 10 + m], Li[m][j], s);
            Li[i][j] = -s;
        }

    for (int i = 0; i < 10; i++)
        for (int j = 0; j < 10; j++) {
            int a0 = (i > j) ? i : j;
            float s = 0.f;
            for (int a = a0; a < 10; a++) s += Li[a][i] * Li[a][j] / D[a];
            g_sig[k * 100 + i * 10 + j] = s;
        }

    float p = 1.f;
#pragma unroll
    for (int a = 0; a < 10; a++) p *= D[a];
    g_det[k] = rsqrtf(p);
}

// ---------------------------------------------------------------------------
// conv2 weight prep. K layout: k = (dy*3+dx)*32 + ci, K=288 (no padding).
// ---------------------------------------------------------------------------
__global__ void k_wprep(const float* __restrict__ w2) {
    int t = blockIdx.x * 256 + threadIdx.x;
    if (t >= 144 * 72) return;
    int kp = t / 72, n = t - kp * 72;
    if (n >= 64) { g_wph[t] = 0u; g_wpl[t] = 0u; return; }

    int w  = kp >> 4;             // window pos 0..8
    int ci = (kp & 15) * 2;       // channel pair
    int dy = w / 3, dx = w - dy * 3;

    unsigned h[2], l[2];
#pragma unroll
    for (int j = 0; j < 2; j++) {
        float v = w2[((n * 32 + ci + j) * 3 + dy) * 3 + dx];
        split_bf16(v, h[j], l[j]);
    }
    g_wph[t] = h[0] | (h[1] << 16);
    g_wpl[t] = l[0] | (l[1] << 16);
}

// ---------------------------------------------------------------------------
// fc1 weight prep (unchanged)
// ---------------------------------------------------------------------------
__global__ void k_f1prep(const float* __restrict__ W) {
    __shared__ unsigned sh[32][132], sl[32][132];
    const int kp0 = blockIdx.x * 32;      // 144 blocks
    const int t = threadIdx.x;            // 256
    const int n = t >> 1, half = t & 1;

    const float* src = W + (size_t)n * 9216 + kp0 * 2 + half * 32;
#pragma unroll
    for (int j = 0; j < 16; j++) {
        float v0 = src[2 * j], v1 = src[2 * j + 1];
        unsigned h0, l0, h1, l1;
        split_bf16(v0, h0, l0);
        split_bf16(v1, h1, l1);
        sh[half * 16 + j][n] = h0 | (h1 << 16);
        sl[half * 16 + j][n] = l0 | (l1 << 16);
    }
    __syncthreads();

    const int kpl = t >> 3, c0 = (t & 7) * 16;
    unsigned* dh = &g_f1h[(size_t)(kp0 + kpl) * 128 + c0];
    unsigned* dl = &g_f1l[(size_t)(kp0 + kpl) * 128 + c0];
#pragma unroll
    for (int j = 0; j < 4; j++) {
        ((uint4*)dh)[j] = ((uint4*)&sh[kpl][c0])[j];
        ((uint4*)dl)[j] = ((uint4*)&sl[kpl][c0])[j];
    }
}

// ---------------------------------------------------------------------------
// Fused conv1 + conv2 + relu + maxpool, split-bf16 HMMA, channel-minor K.
// One block = one image, 288 threads (9 warps).
// Mainloop per ks: ALL frag loads hoisted (32 B + 32 A regs), then 96 MMAs
// in 3 phase-separated sweeps (dependent MMAs 32 apart).
// ---------------------------------------------------------------------------
__global__ void __launch_bounds__(288, 1)
k_convfused(const float* __restrict__ x,
            const float* __restrict__ w1,
            const float* __restrict__ b1,
            const float* __restrict__ cb) {
    const int b   = blockIdx.x;
    const int tid = threadIdx.x;
    const int lane = tid & 31, wid = tid >> 5;
    const int g = lane >> 2, tg = lane & 3;

    extern __shared__ char smraw[];
    unsigned short* sAh = (unsigned short*)smraw;               // [676][34] u16
    unsigned short* sAl = (unsigned short*)(smraw + 46080);
    unsigned* sBh = (unsigned*)(smraw + 92160);                 // [144*72]
    unsigned* sBl = (unsigned*)(smraw + 133632);
    float*    sX  = (float*)(smraw + 175104);                   // [784]
    float*    sW1 = (float*)(smraw + 178240);                   // [288]
    float*    sB1 = (float*)(smraw + 179392);                   // [32]
    const unsigned* sA32h = (const unsigned*)sAh;
    const unsigned* sA32l = (const unsigned*)sAl;

    for (int i = tid; i < 10368; i += 288) { sBh[i] = g_wph[i]; sBl[i] = g_wpl[i]; }
    for (int i = tid; i < 784; i += 288) sX[i] = x[(size_t)b * 784 + i];
    sW1[tid] = w1[tid];
    if (tid < 32) sB1[tid] = b1[tid];
    __syncthreads();

    // conv1 -> relu -> split, channel-interleaved
    for (int idx = tid; idx < 21632; idx += 288) {
        int c = idx / 676, p = idx - c * 676;
        int y = p / 26, xx = p - y * 26;
        float acc = sB1[c];
        const float* xp = sX + y * 28 + xx;
        const float* wp = sW1 + c * 9;
#pragma unroll
        for (int dy = 0; dy < 3; dy++)
#pragma unroll
            for (int dx = 0; dx < 3; dx++)
                acc = fmaf(xp[dy * 28 + dx], wp[dy * 3 + dx], acc);
        float v = fmaxf(acc, 0.f);
        unsigned h, l; split_bf16(v, h, l);
        sAh[p * 34 + c] = (unsigned short)h;
        sAl[p * 34 + c] = (unsigned short)l;
    }
    __syncthreads();

    // per-(strip,row-half) A row base * 17 (u32 stride of a 34-u16 row)
    int base17[4][2];
#pragma unroll
    for (int st = 0; st < 4; st++)
#pragma unroll
        for (int h = 0; h < 2; h++) {
            int m = (wid * 4 + st) * 16 + g + h * 8;
            int quad = m >> 2, e = m & 3;
            int py = quad / 12, px = quad - py * 12;
            base17[st][h] = ((py * 2 + (e >> 1)) * 26 + px * 2 + (e & 1)) * 17;
        }

    float C[4][8][4];
#pragma unroll
    for (int st = 0; st < 4; st++)
#pragma unroll
        for (int nt = 0; nt < 8; nt++)
#pragma unroll
            for (int q = 0; q < 4; q++) C[st][nt][q] = 0.f;

#pragma unroll 1
    for (int ks = 0; ks < 18; ks++) {
        const int w = ks >> 1;
        const int dy = w / 3;
        const int off17 = (dy * 26 + (w - dy * 3)) * 17;
        const int cA = (ks & 1) * 8 + tg;

        // ---- hoisted B fragments (32 regs) ----
        const unsigned* bph = sBh + (ks * 8 + tg) * 72 + g;
        const unsigned* bpl = sBl + (ks * 8 + tg) * 72 + g;
        unsigned B0h[8], B1h[8], B0l[8], B1l[8];
#pragma unroll
        for (int nt = 0; nt < 8; nt++) {
            B0h[nt] = bph[nt * 8];
            B1h[nt] = bph[nt * 8 + 4 * 72];
            B0l[nt] = bpl[nt * 8];
            B1l[nt] = bpl[nt * 8 + 4 * 72];
        }

        // ---- hoisted A fragments for ALL 4 strips (32 regs) ----
        unsigned ah[4][4], al[4][4];
#pragma unroll
        for (int st = 0; st < 4; st++) {
            const int r0 = base17[st][0] + off17 + cA;
            const int r1 = base17[st][1] + off17 + cA;
            ah[st][0] = sA32h[r0];     al[st][0] = sA32l[r0];
            ah[st][1] = sA32h[r1];     al[st][1] = sA32l[r1];
            ah[st][2] = sA32h[r0 + 4]; al[st][2] = sA32l[r0 + 4];
            ah[st][3] = sA32h[r1 + 4]; al[st][3] = sA32l[r1 + 4];
        }

        // ---- 96 MMAs, 3 independent sweeps (RAW pairs 32 apart) ----
#pragma unroll
        for (int st = 0; st < 4; st++)
#pragma unroll
            for (int nt = 0; nt < 8; nt++)
                MMA16816(C[st][nt], ah[st], B0h[nt], B1h[nt]);   // hi*hi
#pragma unroll
        for (int st = 0; st < 4; st++)
#pragma unroll
            for (int nt = 0; nt < 8; nt++)
                MMA16816(C[st][nt], ah[st], B0l[nt], B1l[nt]);   // hi*lo
#pragma unroll
        for (int st = 0; st < 4; st++)
#pragma unroll
            for (int nt = 0; nt < 8; nt++)
                MMA16816(C[st][nt], al[st], B0h[nt], B1h[nt]);   // lo*hi
    }

    // maxpool via shfl + bias + relu + split-pack store
#pragma unroll
    for (int st = 0; st < 4; st++) {
        const int s = wid * 4 + st;
#pragma unroll
        for (int nt = 0; nt < 8; nt++) {
            float v0 = C[st][nt][0], v1 = C[st][nt][1];
            float v2 = C[st][nt][2], v3 = C[st][nt][3];
            v0 = fmaxf(v0, __shfl_xor_sync(0xffffffffu, v0, 4));
            v0 = fmaxf(v0, __shfl_xor_sync(0xffffffffu, v0, 8));
            v1 = fmaxf(v1, __shfl_xor_sync(0xffffffffu, v1, 4));
            v1 = fmaxf(v1, __shfl_xor_sync(0xffffffffu, v1, 8));
            v2 = fmaxf(v2, __shfl_xor_sync(0xffffffffu, v2, 4));
            v2 = fmaxf(v2, __shfl_xor_sync(0xffffffffu, v2, 8));
            v3 = fmaxf(v3, __shfl_xor_sync(0xffffffffu, v3, 4));
            v3 = fmaxf(v3, __shfl_xor_sync(0xffffffffu, v3, 8));
            if ((lane & 12) == 0) {
                int a  = lane >> 4;
                int qA = s * 4 + a, qB = qA + 2;
                int n  = nt * 8 + tg * 2;
                float bn0 = __ldg(cb + n), bn1 = __ldg(cb + n + 1);
                unsigned* o = g_h2 + ((size_t)b * 64 + n) * 144;
                unsigned hh, ll;
                split_bf16(fmaxf(v0 + bn0, 0.f), hh, ll); o[qA]       = hh | (ll << 16);
                split_bf16(fmaxf(v1 + bn1, 0.f), hh, ll); o[144 + qA] = hh | (ll << 16);
                split_bf16(fmaxf(v2 + bn0, 0.f), hh, ll); o[qB]       = hh | (ll << 16);
                split_bf16(fmaxf(v3 + bn1, 0.f), hh, ll); o[144 + qB] = hh | (ll << 16);
            }
        }
    }
}

// ---------------------------------------------------------------------------
// fc1 on tensor cores: relu(h2[4096,9216] @ W[128,9216]^T + b).
// BM=64, BN=64, BK=64; grid 64(m) x 2(n) = 128 blocks, 256 thr (8 warps,
// 4(M) x 2(N), warp tile m16n32); split-bf16 (3 MMAs); reg-prefetch staging.
// Halves W traffic vs BM=32/BN=128.
// ---------------------------------------------------------------------------
__global__ void __launch_bounds__(256)
k_fc1(const float* __restrict__ bias) {
    __shared__ unsigned As[64][68];    // [m][k] packed u32 elems (64 + pad 4)
    __shared__ unsigned Bh[32][72];    // [kp][n] (64 + pad 8)
    __shared__ unsigned Bl[32][72];

    const int tid = threadIdx.x;
    const int lane = tid & 31, warp = tid >> 5;
    const int g = lane >> 2, tg = lane & 3;
    const int mw = warp & 3, nw = warp >> 2;        // 4 x 2 warp grid
    const int m0 = (blockIdx.x >> 1) * 64;
    const int n0 = (blockIdx.x & 1) * 64;

    const int ar = tid >> 2, ac = (tid & 3) * 16;   // A: 4 x uint4 per thread
    const int br = tid >> 3, bc = (tid & 7) * 8;    // B: 2 x uint4 per array

    const unsigned* Ap  = g_h2 + (size_t)(m0 + ar) * 9216 + ac;
    const unsigned* Bph = g_f1h + (size_t)br * 128 + n0 + bc;
    const unsigned* Bpl = g_f1l + (size_t)br * 128 + n0 + bc;

    float C[4][4];
#pragma unroll
    for (int i = 0; i < 4; i++)
#pragma unroll
        for (int j = 0; j < 4; j++) C[i][j] = 0.f;

    uint4 avr[4], bhr[2], blr[2];
#pragma unroll
    for (int j = 0; j < 4; j++) avr[j] = ((const uint4*)Ap)[j];
#pragma unroll
    for (int j = 0; j < 2; j++) {
        bhr[j] = ((const uint4*)Bph)[j];
        blr[j] = ((const uint4*)Bpl)[j];
    }

#pragma unroll 1
    for (int it = 0; it < 144; it++) {
        __syncthreads();
#pragma unroll
        for (int j = 0; j < 4; j++) ((uint4*)&As[ar][ac])[j] = avr[j];
#pragma unroll
        for (int j = 0; j < 2; j++) {
            ((uint4*)&Bh[br][bc])[j] = bhr[j];
            ((uint4*)&Bl[br][bc])[j] = blr[j];
        }
        __syncthreads();

        if (it + 1 < 144) {
            const unsigned* ap = Ap + (it + 1) * 64;
            const unsigned* bp = Bph + (size_t)(it + 1) * 32 * 128;
            const unsigned* lp = Bpl + (size_t)(it + 1) * 32 * 128;
#pragma unroll
            for (int j = 0; j < 4; j++) avr[j] = ((const uint4*)ap)[j];
#pragma unroll
            for (int j = 0; j < 2; j++) {
                bhr[j] = ((const uint4*)bp)[j];
                blr[j] = ((const uint4*)lp)[j];
            }
        }

#pragma unroll
        for (int ks = 0; ks < 4; ks++) {
            const int kc = ks * 16 + 2 * tg;
            const int r0 = mw * 16 + g, r1 = r0 + 8;
            unsigned ah[4], al[4];
            {
                uint2 u = *(const uint2*)&As[r0][kc];
                ah[0] = __byte_perm(u.x, u.y, 0x5410);
                al[0] = __byte_perm(u.x, u.y, 0x7632);
                uint2 v = *(const uint2*)&As[r1][kc];
                ah[1] = __byte_perm(v.x, v.y, 0x5410);
                al[1] = __byte_perm(v.x, v.y, 0x7632);
                uint2 w = *(const uint2*)&As[r0][kc + 8];
                ah[2] = __byte_perm(w.x, w.y, 0x5410);
                al[2] = __byte_perm(w.x, w.y, 0x7632);
                uint2 z = *(const uint2*)&As[r1][kc + 8];
                ah[3] = __byte_perm(z.x, z.y, 0x5410);
                al[3] = __byte_perm(z.x, z.y, 0x7632);
            }
            const int kp = ks * 8 + tg;
#pragma unroll
            for (int nt = 0; nt < 4; nt++) {
                const int n = nw * 32 + nt * 8 + g;
                unsigned b0h = Bh[kp][n],     b1h = Bh[kp + 4][n];
                unsigned b0l = Bl[kp][n],     b1l = Bl[kp + 4][n];
                MMA16816(C[nt], ah, b0h, b1h);
                MMA16816(C[nt], ah, b0l, b1l);
                MMA16816(C[nt], al, b0h, b1h);
            }
        }
    }

    const int m = m0 + mw * 16 + g;
#pragma unroll
    for (int nt = 0; nt < 4; nt++) {
        const int n = n0 + nw * 32 + nt * 8 + 2 * tg;
        float b0 = bias[n], b1 = bias[n + 1];
        g_h3[(size_t)m * 128 + n]           = fmaxf(C[nt][0] + b0, 0.f);
        g_h3[(size_t)m * 128 + n + 1]       = fmaxf(C[nt][1] + b1, 0.f);
        g_h3[(size_t)(m + 8) * 128 + n]     = fmaxf(C[nt][2] + b0, 0.f);
        g_h3[(size_t)(m + 8) * 128 + n + 1] = fmaxf(C[nt][3] + b1, 0.f);
    }
}

// ---------------------------------------------------------------------------
// fc2 + GMM posterior (unchanged, passing)
// ---------------------------------------------------------------------------
__global__ void k_fc2gmm(const float* __restrict__ w2,
                         const float* __restrict__ b2,
                         const float* __restrict__ cen,
                         float* __restrict__ out) {
    extern __shared__ float sm[];
    float* sH = sm;
    float* sW = sH + 128 * 129;
    float* sB = sW + 1280;
    float* sC = sB + 16;
    float* sS = sC + 112;
    float* sD = sS + 1000;

    const int tid = threadIdx.x;
    const int b0 = blockIdx.x * 128;

    for (int i = tid; i < 16384; i += 128)
        sH[(i >> 7) * 129 + (i & 127)] = g_h3[(size_t)b0 * 128 + i];
    for (int i = tid; i < 1280; i += 128) sW[i] = w2[i];
    for (int i = tid; i < 100; i += 128) sC[i] = cen[i];
    for (int i = tid; i < 1000; i += 128) sS[i] = g_sig[i];
    if (tid < 10) { sB[tid] = b2[tid]; sD[tid] = g_det[tid]; }
    __syncthreads();

    const float* h = sH + tid * 129;

    float y[10];
#pragma unroll
    for (int j = 0; j < 10; j++) {
        float s = sB[j];
        const float* wr = sW + j * 128;
#pragma unroll 8
        for (int k = 0; k < 128; k++) s = fmaf(h[k], wr[k], s);
        y[j] = s;
    }

    float expo[10];
    float mx = -3.4e38f;
#pragma unroll 1
    for (int k = 0; k < 10; k++) {
        float diff[10];
#pragma unroll
        for (int d = 0; d < 10; d++) diff[d] = y[d] - sC[k * 10 + d];
        float dist = 0.f;
#pragma unroll
        for (int i = 0; i < 10; i++) {
            float t = 0.f;
#pragma unroll
            for (int j = 0; j < 10; j++)
                t = fmaf(sS[k * 100 + i * 10 + j], diff[j], t);
            dist = fmaf(diff[i], t, dist);
        }
        float e = -0.5f * dist;
        expo[k] = e;
        mx = fmaxf(mx, e);
    }

    float num[10];
    float sum = 0.f;
#pragma unroll
    for (int k = 0; k < 10; k++) {
        float v = sD[k] * expf(expo[k] - mx);
        num[k] = v;
        sum += v;
    }
    float inv = 1.f / sum;

    float* op = out + (size_t)(b0 + tid) * 10;
#pragma unroll
    for (int k = 0; k < 10; k++) op[k] = num[k] * inv;
}

// ---------------------------------------------------------------------------
// kernel_launch
// ---------------------------------------------------------------------------
extern "C" void kernel_launch(void* const* d_in, const int* in_sizes, int n_in,
                              void* d_out, int out_size) {
    const float* x   = (const float*)d_in[0];
    const float* w1  = (const float*)d_in[1];
    const float* b1  = (const float*)d_in[2];
    const float* w2  = (const float*)d_in[3];
    const float* b2  = (const float*)d_in[4];
    const float* fw1 = (const float*)d_in[5];
    const float* fb1 = (const float*)d_in[6];
    const float* fw2 = (const float*)d_in[7];
    const float* fb2 = (const float*)d_in[8];
    const float* cen = (const float*)d_in[9];
    const float* raw = (const float*)d_in[10];
    float* out = (float*)d_out;

    const int SMEM_CONV = 179520;
    const int SMEM_GMM  = (128 * 129 + 1280 + 16 + 112 + 1000 + 16) * 4;
    cudaFuncSetAttribute(k_convfused, cudaFuncAttributeMaxDynamicSharedMemorySize, SMEM_CONV);
    cudaFuncSetAttribute(k_fc2gmm,    cudaFuncAttributeMaxDynamicSharedMemorySize, SMEM_GMM);

    k_gmm_pre<<<1, 32>>>(raw);
    k_wprep<<<(144 * 72 + 255) / 256, 256>>>(w2);
    k_f1prep<<<144, 256>>>(fw1);
    k_convfused<<<BATCH, 288, SMEM_CONV>>>(x, w1, b1, b2);
    k_fc1<<<128, 256>>>(fb1);
    k_fc2gmm<<<BATCH / 128, 128, SMEM_GMM>>>(fw2, fb2, cen, out);
}

// round 8
// speedup vs baseline: 2.2889x; 1.0132x over previous
#include <cuda_runtime.h>
#include <cuda_bf16.h>
#include <cstddef>

#define BATCH 4096

// ---------------------------------------------------------------------------
// Scratch (static __device__; no cudaMalloc allowed)
// ---------------------------------------------------------------------------
__device__ unsigned g_h2[(size_t)BATCH * 9216];   // conv2+pool out, packed (hi|lo<<16) split-bf16
__device__ float    g_h3[(size_t)BATCH * 128];    // fc1 out
__device__ float    g_sig[10 * 10 * 10];          // Sigma_inv
__device__ float    g_det[10];                    // det_scale
__device__ unsigned g_wph[144 * 72];              // conv2 W hi, paired bf16x2, k=(dy*3+dx)*32+ci
__device__ unsigned g_wpl[144 * 72];              // conv2 W lo
__device__ unsigned g_f1h[4608 * 128];            // fc1 W hi, paired bf16x2 [k/2][n]
__device__ unsigned g_f1l[4608 * 128];            // fc1 W lo

// ---------------------------------------------------------------------------
// helpers
// ---------------------------------------------------------------------------
__device__ __forceinline__ void split_bf16(float v, unsigned& h, unsigned& l) {
    __nv_bfloat16 hb = __float2bfloat16_rn(v);
    float hf = __bfloat162float(hb);
    __nv_bfloat16 lb = __float2bfloat16_rn(v - hf);
    h = (unsigned)__bfloat16_as_ushort(hb);
    l = (unsigned)__bfloat16_as_ushort(lb);
}

#define MMA16816(Cr, Ar, b0, b1)                                              \
    asm volatile("mma.sync.aligned.m16n8k16.row.col.f32.bf16.bf16.f32 "       \
                 "{%0,%1,%2,%3}, {%4,%5,%6,%7}, {%8,%9}, {%0,%1,%2,%3};"      \
                 : "+f"(Cr[0]), "+f"(Cr[1]), "+f"(Cr[2]), "+f"(Cr[3])         \
                 : "r"(Ar[0]), "r"(Ar[1]), "r"(Ar[2]), "r"(Ar[3]),            \
                   "r"(b0), "r"(b1))

// ---------------------------------------------------------------------------
// GMM precompute (unchanged)
// ---------------------------------------------------------------------------
__global__ void k_gmm_pre(const float* __restrict__ raw) {
    int k = threadIdx.x;
    if (k >= 10) return;
    const float* R = raw + k * 100;

    float D[10];
#pragma unroll
    for (int i = 0; i < 10; i++) { float r = R[i * 10 + i]; D[i] = r * r + 1e-4f; }

    float Li[10][10];
#pragma unroll
    for (int i = 0; i < 10; i++)
#pragma unroll
        for (int j = 0; j < 10; j++) Li[i][j] = (i == j) ? 1.f : 0.f;

    for (int j = 0; j < 10; j++)
        for (int i = j + 1; i < 10; i++) {
            float s = 0.f;
            for (int m = j; m < i; m++) s = fmaf(R[i * 10 + m], Li[m][j], s);
            Li[i][j] = -s;
        }

    for (int i = 0; i < 10; i++)
        for (int j = 0; j < 10; j++) {
            int a0 = (i > j) ? i : j;
            float s = 0.f;
            for (int a = a0; a < 10; a++) s += Li[a][i] * Li[a][j] / D[a];
            g_sig[k * 100 + i * 10 + j] = s;
        }

    float p = 1.f;
#pragma unroll
    for (int a = 0; a < 10; a++) p *= D[a];
    g_det[k] = rsqrtf(p);
}

// ---------------------------------------------------------------------------
// conv2 weight prep. K layout: k = (dy*3+dx)*32 + ci, K=288 (no padding).
// ---------------------------------------------------------------------------
__global__ void k_wprep(const float* __restrict__ w2) {
    int t = blockIdx.x * 256 + threadIdx.x;
    if (t >= 144 * 72) return;
    int kp = t / 72, n = t - kp * 72;
    if (n >= 64) { g_wph[t] = 0u; g_wpl[t] = 0u; return; }

    int w  = kp >> 4;             // window pos 0..8
    int ci = (kp & 15) * 2;       // channel pair
    int dy = w / 3, dx = w - dy * 3;

    unsigned h[2], l[2];
#pragma unroll
    for (int j = 0; j < 2; j++) {
        float v = w2[((n * 32 + ci + j) * 3 + dy) * 3 + dx];
        split_bf16(v, h[j], l[j]);
    }
    g_wph[t] = h[0] | (h[1] << 16);
    g_wpl[t] = l[0] | (l[1] << 16);
}

// ---------------------------------------------------------------------------
// fc1 weight prep (unchanged)
// ---------------------------------------------------------------------------
__global__ void k_f1prep(const float* __restrict__ W) {
    __shared__ unsigned sh[32][132], sl[32][132];
    const int kp0 = blockIdx.x * 32;      // 144 blocks
    const int t = threadIdx.x;            // 256
    const int n = t >> 1, half = t & 1;

    const float* src = W + (size_t)n * 9216 + kp0 * 2 + half * 32;
#pragma unroll
    for (int j = 0; j < 16; j++) {
        float v0 = src[2 * j], v1 = src[2 * j + 1];
        unsigned h0, l0, h1, l1;
        split_bf16(v0, h0, l0);
        split_bf16(v1, h1, l1);
        sh[half * 16 + j][n] = h0 | (h1 << 16);
        sl[half * 16 + j][n] = l0 | (l1 << 16);
    }
    __syncthreads();

    const int kpl = t >> 3, c0 = (t & 7) * 16;
    unsigned* dh = &g_f1h[(size_t)(kp0 + kpl) * 128 + c0];
    unsigned* dl = &g_f1l[(size_t)(kp0 + kpl) * 128 + c0];
#pragma unroll
    for (int j = 0; j < 4; j++) {
        ((uint4*)dh)[j] = ((uint4*)&sh[kpl][c0])[j];
        ((uint4*)dl)[j] = ((uint4*)&sl[kpl][c0])[j];
    }
}

// ---------------------------------------------------------------------------
// Fused conv1 + conv2 + relu + maxpool, split-bf16 HMMA, channel-minor K.
// One block = one image, 288 threads (9 warps).
// Mainloop per ks: A frags hoisted (32 regs); per n-tile load 4 B regs and
// immediately issue its 12 MMAs (st-major: same-C MMAs 4 issues apart).
// Live regs ~185 < 224 cap -> no spill/remat.
// ---------------------------------------------------------------------------
__global__ void __launch_bounds__(288, 1)
k_convfused(const float* __restrict__ x,
            const float* __restrict__ w1,
            const float* __restrict__ b1,
            const float* __restrict__ cb) {
    const int b   = blockIdx.x;
    const int tid = threadIdx.x;
    const int lane = tid & 31, wid = tid >> 5;
    const int g = lane >> 2, tg = lane & 3;

    extern __shared__ char smraw[];
    unsigned short* sAh = (unsigned short*)smraw;               // [676][34] u16
    unsigned short* sAl = (unsigned short*)(smraw + 46080);
    unsigned* sBh = (unsigned*)(smraw + 92160);                 // [144*72]
    unsigned* sBl = (unsigned*)(smraw + 133632);
    float*    sX  = (float*)(smraw + 175104);                   // [784]
    float*    sW1 = (float*)(smraw + 178240);                   // [288]
    float*    sB1 = (float*)(smraw + 179392);                   // [32]
    const unsigned* sA32h = (const unsigned*)sAh;
    const unsigned* sA32l = (const unsigned*)sAl;

    for (int i = tid; i < 10368; i += 288) { sBh[i] = g_wph[i]; sBl[i] = g_wpl[i]; }
    for (int i = tid; i < 784; i += 288) sX[i] = x[(size_t)b * 784 + i];
    sW1[tid] = w1[tid];
    if (tid < 32) sB1[tid] = b1[tid];
    __syncthreads();

    // conv1 -> relu -> split, channel-interleaved
    for (int idx = tid; idx < 21632; idx += 288) {
        int c = idx / 676, p = idx - c * 676;
        int y = p / 26, xx = p - y * 26;
        float acc = sB1[c];
        const float* xp = sX + y * 28 + xx;
        const float* wp = sW1 + c * 9;
#pragma unroll
        for (int dy = 0; dy < 3; dy++)
#pragma unroll
            for (int dx = 0; dx < 3; dx++)
                acc = fmaf(xp[dy * 28 + dx], wp[dy * 3 + dx], acc);
        float v = fmaxf(acc, 0.f);
        unsigned h, l; split_bf16(v, h, l);
        sAh[p * 34 + c] = (unsigned short)h;
        sAl[p * 34 + c] = (unsigned short)l;
    }
    __syncthreads();

    // per-(strip,row-half) A row base * 17 (u32 stride of a 34-u16 row)
    int base17[4][2];
#pragma unroll
    for (int st = 0; st < 4; st++)
#pragma unroll
        for (int h = 0; h < 2; h++) {
            int m = (wid * 4 + st) * 16 + g + h * 8;
            int quad = m >> 2, e = m & 3;
            int py = quad / 12, px = quad - py * 12;
            base17[st][h] = ((py * 2 + (e >> 1)) * 26 + px * 2 + (e & 1)) * 17;
        }

    float C[4][8][4];
#pragma unroll
    for (int st = 0; st < 4; st++)
#pragma unroll
        for (int nt = 0; nt < 8; nt++)
#pragma unroll
            for (int q = 0; q < 4; q++) C[st][nt][q] = 0.f;

#pragma unroll 1
    for (int ks = 0; ks < 18; ks++) {
        const int w = ks >> 1;
        const int dy = w / 3;
        const int off17 = (dy * 26 + (w - dy * 3)) * 17;
        const int cA = (ks & 1) * 8 + tg;

        // ---- hoisted A fragments for ALL 4 strips (32 regs) ----
        unsigned ah[4][4], al[4][4];
#pragma unroll
        for (int st = 0; st < 4; st++) {
            const int r0 = base17[st][0] + off17 + cA;
            const int r1 = base17[st][1] + off17 + cA;
            ah[st][0] = sA32h[r0];     al[st][0] = sA32l[r0];
            ah[st][1] = sA32h[r1];     al[st][1] = sA32l[r1];
            ah[st][2] = sA32h[r0 + 4]; al[st][2] = sA32l[r0 + 4];
            ah[st][3] = sA32h[r1 + 4]; al[st][3] = sA32l[r1 + 4];
        }

        // ---- per n-tile: 4 B regs live, 12 MMAs immediately ----
        const unsigned* bph = sBh + (ks * 8 + tg) * 72 + g;
        const unsigned* bpl = sBl + (ks * 8 + tg) * 72 + g;
#pragma unroll
        for (int nt = 0; nt < 8; nt++) {
            const unsigned B0h = bph[nt * 8];
            const unsigned B1h = bph[nt * 8 + 4 * 72];
            const unsigned B0l = bpl[nt * 8];
            const unsigned B1l = bpl[nt * 8 + 4 * 72];
#pragma unroll
            for (int st = 0; st < 4; st++)
                MMA16816(C[st][nt], ah[st], B0h, B1h);   // hi*hi
#pragma unroll
            for (int st = 0; st < 4; st++)
                MMA16816(C[st][nt], ah[st], B0l, B1l);   // hi*lo
#pragma unroll
            for (int st = 0; st < 4; st++)
                MMA16816(C[st][nt], al[st], B0h, B1h);   // lo*hi
        }
    }

    // maxpool via shfl + bias + relu + split-pack store
#pragma unroll
    for (int st = 0; st < 4; st++) {
        const int s = wid * 4 + st;
#pragma unroll
        for (int nt = 0; nt < 8; nt++) {
            float v0 = C[st][nt][0], v1 = C[st][nt][1];
            float v2 = C[st][nt][2], v3 = C[st][nt][3];
            v0 = fmaxf(v0, __shfl_xor_sync(0xffffffffu, v0, 4));
            v0 = fmaxf(v0, __shfl_xor_sync(0xffffffffu, v0, 8));
            v1 = fmaxf(v1, __shfl_xor_sync(0xffffffffu, v1, 4));
            v1 = fmaxf(v1, __shfl_xor_sync(0xffffffffu, v1, 8));
            v2 = fmaxf(v2, __shfl_xor_sync(0xffffffffu, v2, 4));
            v2 = fmaxf(v2, __shfl_xor_sync(0xffffffffu, v2, 8));
            v3 = fmaxf(v3, __shfl_xor_sync(0xffffffffu, v3, 4));
            v3 = fmaxf(v3, __shfl_xor_sync(0xffffffffu, v3, 8));
            if ((lane & 12) == 0) {
                int a  = lane >> 4;
                int qA = s * 4 + a, qB = qA + 2;
                int n  = nt * 8 + tg * 2;
                float bn0 = __ldg(cb + n), bn1 = __ldg(cb + n + 1);
                unsigned* o = g_h2 + ((size_t)b * 64 + n) * 144;
                unsigned hh, ll;
                split_bf16(fmaxf(v0 + bn0, 0.f), hh, ll); o[qA]       = hh | (ll << 16);
                split_bf16(fmaxf(v1 + bn1, 0.f), hh, ll); o[144 + qA] = hh | (ll << 16);
                split_bf16(fmaxf(v2 + bn0, 0.f), hh, ll); o[qB]       = hh | (ll << 16);
                split_bf16(fmaxf(v3 + bn1, 0.f), hh, ll); o[144 + qB] = hh | (ll << 16);
            }
        }
    }
}

// ---------------------------------------------------------------------------
// fc1 on tensor cores (unchanged from R7): BM=64, BN=64, BK=64.
// ---------------------------------------------------------------------------
__global__ void __launch_bounds__(256)
k_fc1(const float* __restrict__ bias) {
    __shared__ unsigned As[64][68];
    __shared__ unsigned Bh[32][72];
    __shared__ unsigned Bl[32][72];

    const int tid = threadIdx.x;
    const int lane = tid & 31, warp = tid >> 5;
    const int g = lane >> 2, tg = lane & 3;
    const int mw = warp & 3, nw = warp >> 2;
    const int m0 = (blockIdx.x >> 1) * 64;
    const int n0 = (blockIdx.x & 1) * 64;

    const int ar = tid >> 2, ac = (tid & 3) * 16;
    const int br = tid >> 3, bc = (tid & 7) * 8;

    const unsigned* Ap  = g_h2 + (size_t)(m0 + ar) * 9216 + ac;
    const unsigned* Bph = g_f1h + (size_t)br * 128 + n0 + bc;
    const unsigned* Bpl = g_f1l + (size_t)br * 128 + n0 + bc;

    float C[4][4];
#pragma unroll
    for (int i = 0; i < 4; i++)
#pragma unroll
        for (int j = 0; j < 4; j++) C[i][j] = 0.f;

    uint4 avr[4], bhr[2], blr[2];
#pragma unroll
    for (int j = 0; j < 4; j++) avr[j] = ((const uint4*)Ap)[j];
#pragma unroll
    for (int j = 0; j < 2; j++) {
        bhr[j] = ((const uint4*)Bph)[j];
        blr[j] = ((const uint4*)Bpl)[j];
    }

#pragma unroll 1
    for (int it = 0; it < 144; it++) {
        __syncthreads();
#pragma unroll
        for (int j = 0; j < 4; j++) ((uint4*)&As[ar][ac])[j] = avr[j];
#pragma unroll
        for (int j = 0; j < 2; j++) {
            ((uint4*)&Bh[br][bc])[j] = bhr[j];
            ((uint4*)&Bl[br][bc])[j] = blr[j];
        }
        __syncthreads();

        if (it + 1 < 144) {
            const unsigned* ap = Ap + (it + 1) * 64;
            const unsigned* bp = Bph + (size_t)(it + 1) * 32 * 128;
            const unsigned* lp = Bpl + (size_t)(it + 1) * 32 * 128;
#pragma unroll
            for (int j = 0; j < 4; j++) avr[j] = ((const uint4*)ap)[j];
#pragma unroll
            for (int j = 0; j < 2; j++) {
                bhr[j] = ((const uint4*)bp)[j];
                blr[j] = ((const uint4*)lp)[j];
            }
        }

#pragma unroll
        for (int ks = 0; ks < 4; ks++) {
            const int kc = ks * 16 + 2 * tg;
            const int r0 = mw * 16 + g, r1 = r0 + 8;
            unsigned ah[4], al[4];
            {
                uint2 u = *(const uint2*)&As[r0][kc];
                ah[0] = __byte_perm(u.x, u.y, 0x5410);
                al[0] = __byte_perm(u.x, u.y, 0x7632);
                uint2 v = *(const uint2*)&As[r1][kc];
                ah[1] = __byte_perm(v.x, v.y, 0x5410);
                al[1] = __byte_perm(v.x, v.y, 0x7632);
                uint2 w = *(const uint2*)&As[r0][kc + 8];
                ah[2] = __byte_perm(w.x, w.y, 0x5410);
                al[2] = __byte_perm(w.x, w.y, 0x7632);
                uint2 z = *(const uint2*)&As[r1][kc + 8];
                ah[3] = __byte_perm(z.x, z.y, 0x5410);
                al[3] = __byte_perm(z.x, z.y, 0x7632);
            }
            const int kp = ks * 8 + tg;
#pragma unroll
            for (int nt = 0; nt < 4; nt++) {
                const int n = nw * 32 + nt * 8 + g;
                unsigned b0h = Bh[kp][n],     b1h = Bh[kp + 4][n];
                unsigned b0l = Bl[kp][n],     b1l = Bl[kp + 4][n];
                MMA16816(C[nt], ah, b0h, b1h);
                MMA16816(C[nt], ah, b0l, b1l);
                MMA16816(C[nt], al, b0h, b1h);
            }
        }
    }

    const int m = m0 + mw * 16 + g;
#pragma unroll
    for (int nt = 0; nt < 4; nt++) {
        const int n = n0 + nw * 32 + nt * 8 + 2 * tg;
        float b0 = bias[n], b1 = bias[n + 1];
        g_h3[(size_t)m * 128 + n]           = fmaxf(C[nt][0] + b0, 0.f);
        g_h3[(size_t)m * 128 + n + 1]       = fmaxf(C[nt][1] + b1, 0.f);
        g_h3[(size_t)(m + 8) * 128 + n]     = fmaxf(C[nt][2] + b0, 0.f);
        g_h3[(size_t)(m + 8) * 128 + n + 1] = fmaxf(C[nt][3] + b1, 0.f);
    }
}

// ---------------------------------------------------------------------------
// fc2 + GMM posterior (unchanged, passing)
// ---------------------------------------------------------------------------
__global__ void k_fc2gmm(const float* __restrict__ w2,
                         const float* __restrict__ b2,
                         const float* __restrict__ cen,
                         float* __restrict__ out) {
    extern __shared__ float sm[];
    float* sH = sm;
    float* sW = sH + 128 * 129;
    float* sB = sW + 1280;
    float* sC = sB + 16;
    float* sS = sC + 112;
    float* sD = sS + 1000;

    const int tid = threadIdx.x;
    const int b0 = blockIdx.x * 128;

    for (int i = tid; i < 16384; i += 128)
        sH[(i >> 7) * 129 + (i & 127)] = g_h3[(size_t)b0 * 128 + i];
    for (int i = tid; i < 1280; i += 128) sW[i] = w2[i];
    for (int i = tid; i < 100; i += 128) sC[i] = cen[i];
    for (int i = tid; i < 1000; i += 128) sS[i] = g_sig[i];
    if (tid < 10) { sB[tid] = b2[tid]; sD[tid] = g_det[tid]; }
    __syncthreads();

    const float* h = sH + tid * 129;

    float y[10];
#pragma unroll
    for (int j = 0; j < 10; j++) {
        float s = sB[j];
        const float* wr = sW + j * 128;
#pragma unroll 8
        for (int k = 0; k < 128; k++) s = fmaf(h[k], wr[k], s);
        y[j] = s;
    }

    float expo[10];
    float mx = -3.4e38f;
#pragma unroll 1
    for (int k = 0; k < 10; k++) {
        float diff[10];
#pragma unroll
        for (int d = 0; d < 10; d++) diff[d] = y[d] - sC[k * 10 + d];
        float dist = 0.f;
#pragma unroll
        for (int i = 0; i < 10; i++) {
            float t = 0.f;
#pragma unroll
            for (int j = 0; j < 10; j++)
                t = fmaf(sS[k * 100 + i * 10 + j], diff[j], t);
            dist = fmaf(diff[i], t, dist);
        }
        float e = -0.5f * dist;
        expo[k] = e;
        mx = fmaxf(mx, e);
    }

    float num[10];
    float sum = 0.f;
#pragma unroll
    for (int k = 0; k < 10; k++) {
        float v = sD[k] * expf(expo[k] - mx);
        num[k] = v;
        sum += v;
    }
    float inv = 1.f / sum;

    float* op = out + (size_t)(b0 + tid) * 10;
#pragma unroll
    for (int k = 0; k < 10; k++) op[k] = num[k] * inv;
}

// ---------------------------------------------------------------------------
// kernel_launch
// ---------------------------------------------------------------------------
extern "C" void kernel_launch(void* const* d_in, const int* in_sizes, int n_in,
                              void* d_out, int out_size) {
    const float* x   = (const float*)d_in[0];
    const float* w1  = (const float*)d_in[1];
    const float* b1  = (const float*)d_in[2];
    const float* w2  = (const float*)d_in[3];
    const float* b2  = (const float*)d_in[4];
    const float* fw1 = (const float*)d_in[5];
    const float* fb1 = (const float*)d_in[6];
    const float* fw2 = (const float*)d_in[7];
    const float* fb2 = (const float*)d_in[8];
    const float* cen = (const float*)d_in[9];
    const float* raw = (const float*)d_in[10];
    float* out = (float*)d_out;

    const int SMEM_CONV = 179520;
    const int SMEM_GMM  = (128 * 129 + 1280 + 16 + 112 + 1000 + 16) * 4;
    cudaFuncSetAttribute(k_convfused, cudaFuncAttributeMaxDynamicSharedMemorySize, SMEM_CONV);
    cudaFuncSetAttribute(k_fc2gmm,    cudaFuncAttributeMaxDynamicSharedMemorySize, SMEM_GMM);

    k_gmm_pre<<<1, 32>>>(raw);
    k_wprep<<<(144 * 72 + 255) / 256, 256>>>(w2);
    k_f1prep<<<144, 256>>>(fw1);
    k_convfused<<<BATCH, 288, SMEM_CONV>>>(x, w1, b1, b2);
    k_fc1<<<128, 256>>>(fb1);
    k_fc2gmm<<<BATCH / 128, 128, SMEM_GMM>>>(fw2, fb2, cen, out);
}

// round 9
// speedup vs baseline: 2.5875x; 1.1305x over previous
#include <cuda_runtime.h>
#include <cuda_bf16.h>
#include <cstddef>

#define BATCH 4096

// ---------------------------------------------------------------------------
// Scratch (static __device__; no cudaMalloc allowed)
// ---------------------------------------------------------------------------
__device__ unsigned g_h2[(size_t)BATCH * 9216];   // conv2+pool out, packed (hi|lo<<16) split-bf16
__device__ float    g_h3[(size_t)BATCH * 128];    // fc1 out
__device__ float    g_sig[10 * 10 * 10];          // Sigma_inv
__device__ float    g_det[10];                    // det_scale
__device__ unsigned g_wph[144 * 72];              // conv2 W hi, paired bf16x2, k=(dy*3+dx)*32+ci
__device__ unsigned g_wpl[144 * 72];              // conv2 W lo
__device__ unsigned g_f1h[4608 * 128];            // fc1 W hi, paired bf16x2 [k/2][n]
__device__ unsigned g_f1l[4608 * 128];            // fc1 W lo

// ---------------------------------------------------------------------------
// helpers
// ---------------------------------------------------------------------------
__device__ __forceinline__ void split_bf16(float v, unsigned& h, unsigned& l) {
    __nv_bfloat16 hb = __float2bfloat16_rn(v);
    float hf = __bfloat162float(hb);
    __nv_bfloat16 lb = __float2bfloat16_rn(v - hf);
    h = (unsigned)__bfloat16_as_ushort(hb);
    l = (unsigned)__bfloat16_as_ushort(lb);
}

#define MMA16816(Cr, Ar, b0, b1)                                              \
    asm volatile("mma.sync.aligned.m16n8k16.row.col.f32.bf16.bf16.f32 "       \
                 "{%0,%1,%2,%3}, {%4,%5,%6,%7}, {%8,%9}, {%0,%1,%2,%3};"      \
                 : "+f"(Cr[0]), "+f"(Cr[1]), "+f"(Cr[2]), "+f"(Cr[3])         \
                 : "r"(Ar[0]), "r"(Ar[1]), "r"(Ar[2]), "r"(Ar[3]),            \
                   "r"(b0), "r"(b1))

// ---------------------------------------------------------------------------
// GMM precompute (unchanged)
// ---------------------------------------------------------------------------
__global__ void k_gmm_pre(const float* __restrict__ raw) {
    int k = threadIdx.x;
    if (k >= 10) return;
    const float* R = raw + k * 100;

    float D[10];
#pragma unroll
    for (int i = 0; i < 10; i++) { float r = R[i * 10 + i]; D[i] = r * r + 1e-4f; }

    float Li[10][10];
#pragma unroll
    for (int i = 0; i < 10; i++)
#pragma unroll
        for (int j = 0; j < 10; j++) Li[i][j] = (i == j) ? 1.f : 0.f;

    for (int j = 0; j < 10; j++)
        for (int i = j + 1; i < 10; i++) {
            float s = 0.f;
            for (int m = j; m < i; m++) s = fmaf(R[i * 10 + m], Li[m][j], s);
            Li[i][j] = -s;
        }

    for (int i = 0; i < 10; i++)
        for (int j = 0; j < 10; j++) {
            int a0 = (i > j) ? i : j;
            float s = 0.f;
            for (int a = a0; a < 10; a++) s += Li[a][i] * Li[a][j] / D[a];
            g_sig[k * 100 + i * 10 + j] = s;
        }

    float p = 1.f;
#pragma unroll
    for (int a = 0; a < 10; a++) p *= D[a];
    g_det[k] = rsqrtf(p);
}

// ---------------------------------------------------------------------------
// conv2 weight prep. K layout: k = (dy*3+dx)*32 + ci, K=288 (no padding).
// ---------------------------------------------------------------------------
__global__ void k_wprep(const float* __restrict__ w2) {
    int t = blockIdx.x * 256 + threadIdx.x;
    if (t >= 144 * 72) return;
    int kp = t / 72, n = t - kp * 72;
    if (n >= 64) { g_wph[t] = 0u; g_wpl[t] = 0u; return; }

    int w  = kp >> 4;             // window pos 0..8
    int ci = (kp & 15) * 2;       // channel pair
    int dy = w / 3, dx = w - dy * 3;

    unsigned h[2], l[2];
#pragma unroll
    for (int j = 0; j < 2; j++) {
        float v = w2[((n * 32 + ci + j) * 3 + dy) * 3 + dx];
        split_bf16(v, h[j], l[j]);
    }
    g_wph[t] = h[0] | (h[1] << 16);
    g_wpl[t] = l[0] | (l[1] << 16);
}

// ---------------------------------------------------------------------------
// fc1 weight prep (unchanged)
// ---------------------------------------------------------------------------
__global__ void k_f1prep(const float* __restrict__ W) {
    __shared__ unsigned sh[32][132], sl[32][132];
    const int kp0 = blockIdx.x * 32;      // 144 blocks
    const int t = threadIdx.x;            // 256
    const int n = t >> 1, half = t & 1;

    const float* src = W + (size_t)n * 9216 + kp0 * 2 + half * 32;
#pragma unroll
    for (int j = 0; j < 16; j++) {
        float v0 = src[2 * j], v1 = src[2 * j + 1];
        unsigned h0, l0, h1, l1;
        split_bf16(v0, h0, l0);
        split_bf16(v1, h1, l1);
        sh[half * 16 + j][n] = h0 | (h1 << 16);
        sl[half * 16 + j][n] = l0 | (l1 << 16);
    }
    __syncthreads();

    const int kpl = t >> 3, c0 = (t & 7) * 16;
    unsigned* dh = &g_f1h[(size_t)(kp0 + kpl) * 128 + c0];
    unsigned* dl = &g_f1l[(size_t)(kp0 + kpl) * 128 + c0];
#pragma unroll
    for (int j = 0; j < 4; j++) {
        ((uint4*)dh)[j] = ((uint4*)&sh[kpl][c0])[j];
        ((uint4*)dl)[j] = ((uint4*)&sl[kpl][c0])[j];
    }
}

// ---------------------------------------------------------------------------
// Fused conv1 + conv2 + relu + maxpool, split-bf16 HMMA, channel-minor K.
// One block = one image, 576 threads (18 warps) -> 4.5 warps/SMSP.
// Each warp: 2 m16-strips x 8 n8-tiles (C = 64 regs/thread).
// ---------------------------------------------------------------------------
__global__ void __launch_bounds__(576, 1)
k_convfused(const float* __restrict__ x,
            const float* __restrict__ w1,
            const float* __restrict__ b1,
            const float* __restrict__ cb) {
    const int b   = blockIdx.x;
    const int tid = threadIdx.x;
    const int lane = tid & 31, wid = tid >> 5;
    const int g = lane >> 2, tg = lane & 3;

    extern __shared__ char smraw[];
    unsigned short* sAh = (unsigned short*)smraw;               // [676][34] u16
    unsigned short* sAl = (unsigned short*)(smraw + 46080);
    unsigned* sBh = (unsigned*)(smraw + 92160);                 // [144*72]
    unsigned* sBl = (unsigned*)(smraw + 133632);
    float*    sX  = (float*)(smraw + 175104);                   // [784]
    float*    sW1 = (float*)(smraw + 178240);                   // [288]
    float*    sB1 = (float*)(smraw + 179392);                   // [32]
    const unsigned* sA32h = (const unsigned*)sAh;
    const unsigned* sA32l = (const unsigned*)sAl;

    for (int i = tid; i < 10368; i += 576) { sBh[i] = g_wph[i]; sBl[i] = g_wpl[i]; }
    for (int i = tid; i < 784; i += 576) sX[i] = x[(size_t)b * 784 + i];
    if (tid < 288) sW1[tid] = w1[tid];
    if (tid < 32) sB1[tid] = b1[tid];
    __syncthreads();

    // conv1 -> relu -> split, channel-interleaved
    for (int idx = tid; idx < 21632; idx += 576) {
        int c = idx / 676, p = idx - c * 676;
        int y = p / 26, xx = p - y * 26;
        float acc = sB1[c];
        const float* xp = sX + y * 28 + xx;
        const float* wp = sW1 + c * 9;
#pragma unroll
        for (int dy = 0; dy < 3; dy++)
#pragma unroll
            for (int dx = 0; dx < 3; dx++)
                acc = fmaf(xp[dy * 28 + dx], wp[dy * 3 + dx], acc);
        float v = fmaxf(acc, 0.f);
        unsigned h, l; split_bf16(v, h, l);
        sAh[p * 34 + c] = (unsigned short)h;
        sAl[p * 34 + c] = (unsigned short)l;
    }
    __syncthreads();

    // per-(strip,row-half) A row base * 17 (u32 stride of a 34-u16 row)
    int base17[2][2];
#pragma unroll
    for (int st = 0; st < 2; st++)
#pragma unroll
        for (int h = 0; h < 2; h++) {
            int m = (wid * 2 + st) * 16 + g + h * 8;
            int quad = m >> 2, e = m & 3;
            int py = quad / 12, px = quad - py * 12;
            base17[st][h] = ((py * 2 + (e >> 1)) * 26 + px * 2 + (e & 1)) * 17;
        }

    float C[2][8][4];
#pragma unroll
    for (int st = 0; st < 2; st++)
#pragma unroll
        for (int nt = 0; nt < 8; nt++)
#pragma unroll
            for (int q = 0; q < 4; q++) C[st][nt][q] = 0.f;

#pragma unroll 1
    for (int ks = 0; ks < 18; ks++) {
        const int w = ks >> 1;
        const int dy = w / 3;
        const int off17 = (dy * 26 + (w - dy * 3)) * 17;
        const int cA = (ks & 1) * 8 + tg;

        // ---- hoisted A fragments for both strips (16 regs) ----
        unsigned ah[2][4], al[2][4];
#pragma unroll
        for (int st = 0; st < 2; st++) {
            const int r0 = base17[st][0] + off17 + cA;
            const int r1 = base17[st][1] + off17 + cA;
            ah[st][0] = sA32h[r0];     al[st][0] = sA32l[r0];
            ah[st][1] = sA32h[r1];     al[st][1] = sA32l[r1];
            ah[st][2] = sA32h[r0 + 4]; al[st][2] = sA32l[r0 + 4];
            ah[st][3] = sA32h[r1 + 4]; al[st][3] = sA32l[r1 + 4];
        }

        // ---- per n-tile: 4 B regs live, 6 MMAs immediately ----
        const unsigned* bph = sBh + (ks * 8 + tg) * 72 + g;
        const unsigned* bpl = sBl + (ks * 8 + tg) * 72 + g;
#pragma unroll
        for (int nt = 0; nt < 8; nt++) {
            const unsigned B0h = bph[nt * 8];
            const unsigned B1h = bph[nt * 8 + 4 * 72];
            const unsigned B0l = bpl[nt * 8];
            const unsigned B1l = bpl[nt * 8 + 4 * 72];
            MMA16816(C[0][nt], ah[0], B0h, B1h);
            MMA16816(C[1][nt], ah[1], B0h, B1h);
            MMA16816(C[0][nt], ah[0], B0l, B1l);
            MMA16816(C[1][nt], ah[1], B0l, B1l);
            MMA16816(C[0][nt], al[0], B0h, B1h);
            MMA16816(C[1][nt], al[1], B0h, B1h);
        }
    }

    // maxpool via shfl + bias + relu + split-pack store
#pragma unroll
    for (int st = 0; st < 2; st++) {
        const int s = wid * 2 + st;
#pragma unroll
        for (int nt = 0; nt < 8; nt++) {
            float v0 = C[st][nt][0], v1 = C[st][nt][1];
            float v2 = C[st][nt][2], v3 = C[st][nt][3];
            v0 = fmaxf(v0, __shfl_xor_sync(0xffffffffu, v0, 4));
            v0 = fmaxf(v0, __shfl_xor_sync(0xffffffffu, v0, 8));
            v1 = fmaxf(v1, __shfl_xor_sync(0xffffffffu, v1, 4));
            v1 = fmaxf(v1, __shfl_xor_sync(0xffffffffu, v1, 8));
            v2 = fmaxf(v2, __shfl_xor_sync(0xffffffffu, v2, 4));
            v2 = fmaxf(v2, __shfl_xor_sync(0xffffffffu, v2, 8));
            v3 = fmaxf(v3, __shfl_xor_sync(0xffffffffu, v3, 4));
            v3 = fmaxf(v3, __shfl_xor_sync(0xffffffffu, v3, 8));
            if ((lane & 12) == 0) {
                int a  = lane >> 4;
                int qA = s * 4 + a, qB = qA + 2;
                int n  = nt * 8 + tg * 2;
                float bn0 = __ldg(cb + n), bn1 = __ldg(cb + n + 1);
                unsigned* o = g_h2 + ((size_t)b * 64 + n) * 144;
                unsigned hh, ll;
                split_bf16(fmaxf(v0 + bn0, 0.f), hh, ll); o[qA]       = hh | (ll << 16);
                split_bf16(fmaxf(v1 + bn1, 0.f), hh, ll); o[144 + qA] = hh | (ll << 16);
                split_bf16(fmaxf(v2 + bn0, 0.f), hh, ll); o[qB]       = hh | (ll << 16);
                split_bf16(fmaxf(v3 + bn1, 0.f), hh, ll); o[144 + qB] = hh | (ll << 16);
            }
        }
    }
}

// ---------------------------------------------------------------------------
// fc1 on tensor cores (unchanged): BM=64, BN=64, BK=64.
// ---------------------------------------------------------------------------
__global__ void __launch_bounds__(256)
k_fc1(const float* __restrict__ bias) {
    __shared__ unsigned As[64][68];
    __shared__ unsigned Bh[32][72];
    __shared__ unsigned Bl[32][72];

    const int tid = threadIdx.x;
    const int lane = tid & 31, warp = tid >> 5;
    const int g = lane >> 2, tg = lane & 3;
    const int mw = warp & 3, nw = warp >> 2;
    const int m0 = (blockIdx.x >> 1) * 64;
    const int n0 = (blockIdx.x & 1) * 64;

    const int ar = tid >> 2, ac = (tid & 3) * 16;
    const int br = tid >> 3, bc = (tid & 7) * 8;

    const unsigned* Ap  = g_h2 + (size_t)(m0 + ar) * 9216 + ac;
    const unsigned* Bph = g_f1h + (size_t)br * 128 + n0 + bc;
    const unsigned* Bpl = g_f1l + (size_t)br * 128 + n0 + bc;

    float C[4][4];
#pragma unroll
    for (int i = 0; i < 4; i++)
#pragma unroll
        for (int j = 0; j < 4; j++) C[i][j] = 0.f;

    uint4 avr[4], bhr[2], blr[2];
#pragma unroll
    for (int j = 0; j < 4; j++) avr[j] = ((const uint4*)Ap)[j];
#pragma unroll
    for (int j = 0; j < 2; j++) {
        bhr[j] = ((const uint4*)Bph)[j];
        blr[j] = ((const uint4*)Bpl)[j];
    }

#pragma unroll 1
    for (int it = 0; it < 144; it++) {
        __syncthreads();
#pragma unroll
        for (int j = 0; j < 4; j++) ((uint4*)&As[ar][ac])[j] = avr[j];
#pragma unroll
        for (int j = 0; j < 2; j++) {
            ((uint4*)&Bh[br][bc])[j] = bhr[j];
            ((uint4*)&Bl[br][bc])[j] = blr[j];
        }
        __syncthreads();

        if (it + 1 < 144) {
            const unsigned* ap = Ap + (it + 1) * 64;
            const unsigned* bp = Bph + (size_t)(it + 1) * 32 * 128;
            const unsigned* lp = Bpl + (size_t)(it + 1) * 32 * 128;
#pragma unroll
            for (int j = 0; j < 4; j++) avr[j] = ((const uint4*)ap)[j];
#pragma unroll
            for (int j = 0; j < 2; j++) {
                bhr[j] = ((const uint4*)bp)[j];
                blr[j] = ((const uint4*)lp)[j];
            }
        }

#pragma unroll
        for (int ks = 0; ks < 4; ks++) {
            const int kc = ks * 16 + 2 * tg;
            const int r0 = mw * 16 + g, r1 = r0 + 8;
            unsigned ah[4], al[4];
            {
                uint2 u = *(const uint2*)&As[r0][kc];
                ah[0] = __byte_perm(u.x, u.y, 0x5410);
                al[0] = __byte_perm(u.x, u.y, 0x7632);
                uint2 v = *(const uint2*)&As[r1][kc];
                ah[1] = __byte_perm(v.x, v.y, 0x5410);
                al[1] = __byte_perm(v.x, v.y, 0x7632);
                uint2 w = *(const uint2*)&As[r0][kc + 8];
                ah[2] = __byte_perm(w.x, w.y, 0x5410);
                al[2] = __byte_perm(w.x, w.y, 0x7632);
                uint2 z = *(const uint2*)&As[r1][kc + 8];
                ah[3] = __byte_perm(z.x, z.y, 0x5410);
                al[3] = __byte_perm(z.x, z.y, 0x7632);
            }
            const int kp = ks * 8 + tg;
#pragma unroll
            for (int nt = 0; nt < 4; nt++) {
                const int n = nw * 32 + nt * 8 + g;
                unsigned b0h = Bh[kp][n],     b1h = Bh[kp + 4][n];
                unsigned b0l = Bl[kp][n],     b1l = Bl[kp + 4][n];
                MMA16816(C[nt], ah, b0h, b1h);
                MMA16816(C[nt], ah, b0l, b1l);
                MMA16816(C[nt], al, b0h, b1h);
            }
        }
    }

    const int m = m0 + mw * 16 + g;
#pragma unroll
    for (int nt = 0; nt < 4; nt++) {
        const int n = n0 + nw * 32 + nt * 8 + 2 * tg;
        float b0 = bias[n], b1 = bias[n + 1];
        g_h3[(size_t)m * 128 + n]           = fmaxf(C[nt][0] + b0, 0.f);
        g_h3[(size_t)m * 128 + n + 1]       = fmaxf(C[nt][1] + b1, 0.f);
        g_h3[(size_t)(m + 8) * 128 + n]     = fmaxf(C[nt][2] + b0, 0.f);
        g_h3[(size_t)(m + 8) * 128 + n + 1] = fmaxf(C[nt][3] + b1, 0.f);
    }
}

// ---------------------------------------------------------------------------
// fc2 + GMM posterior (unchanged, passing)
// ---------------------------------------------------------------------------
__global__ void k_fc2gmm(const float* __restrict__ w2,
                         const float* __restrict__ b2,
                         const float* __restrict__ cen,
                         float* __restrict__ out) {
    extern __shared__ float sm[];
    float* sH = sm;
    float* sW = sH + 128 * 129;
    float* sB = sW + 1280;
    float* sC = sB + 16;
    float* sS = sC + 112;
    float* sD = sS + 1000;

    const int tid = threadIdx.x;
    const int b0 = blockIdx.x * 128;

    for (int i = tid; i < 16384; i += 128)
        sH[(i >> 7) * 129 + (i & 127)] = g_h3[(size_t)b0 * 128 + i];
    for (int i = tid; i < 1280; i += 128) sW[i] = w2[i];
    for (int i = tid; i < 100; i += 128) sC[i] = cen[i];
    for (int i = tid; i < 1000; i += 128) sS[i] = g_sig[i];
    if (tid < 10) { sB[tid] = b2[tid]; sD[tid] = g_det[tid]; }
    __syncthreads();

    const float* h = sH + tid * 129;

    float y[10];
#pragma unroll
    for (int j = 0; j < 10; j++) {
        float s = sB[j];
        const float* wr = sW + j * 128;
#pragma unroll 8
        for (int k = 0; k < 128; k++) s = fmaf(h[k], wr[k], s);
        y[j] = s;
    }

    float expo[10];
    float mx = -3.4e38f;
#pragma unroll 1
    for (int k = 0; k < 10; k++) {
        float diff[10];
#pragma unroll
        for (int d = 0; d < 10; d++) diff[d] = y[d] - sC[k * 10 + d];
        float dist = 0.f;
#pragma unroll
        for (int i = 0; i < 10; i++) {
            float t = 0.f;
#pragma unroll
            for (int j = 0; j < 10; j++)
                t = fmaf(sS[k * 100 + i * 10 + j], diff[j], t);
            dist = fmaf(diff[i], t, dist);
        }
        float e = -0.5f * dist;
        expo[k] = e;
        mx = fmaxf(mx, e);
    }

    float num[10];
    float sum = 0.f;
#pragma unroll
    for (int k = 0; k < 10; k++) {
        float v = sD[k] * expf(expo[k] - mx);
        num[k] = v;
        sum += v;
    }
    float inv = 1.f / sum;

    float* op = out + (size_t)(b0 + tid) * 10;
#pragma unroll
    for (int k = 0; k < 10; k++) op[k] = num[k] * inv;
}

// ---------------------------------------------------------------------------
// kernel_launch
// ---------------------------------------------------------------------------
extern "C" void kernel_launch(void* const* d_in, const int* in_sizes, int n_in,
                              void* d_out, int out_size) {
    const float* x   = (const float*)d_in[0];
    const float* w1  = (const float*)d_in[1];
    const float* b1  = (const float*)d_in[2];
    const float* w2  = (const float*)d_in[3];
    const float* b2  = (const float*)d_in[4];
    const float* fw1 = (const float*)d_in[5];
    const float* fb1 = (const float*)d_in[6];
    const float* fw2 = (const float*)d_in[7];
    const float* fb2 = (const float*)d_in[8];
    const float* cen = (const float*)d_in[9];
    const float* raw = (const float*)d_in[10];
    float* out = (float*)d_out;

    const int SMEM_CONV = 179520;
    const int SMEM_GMM  = (128 * 129 + 1280 + 16 + 112 + 1000 + 16) * 4;
    cudaFuncSetAttribute(k_convfused, cudaFuncAttributeMaxDynamicSharedMemorySize, SMEM_CONV);
    cudaFuncSetAttribute(k_fc2gmm,    cudaFuncAttributeMaxDynamicSharedMemorySize, SMEM_GMM);

    k_gmm_pre<<<1, 32>>>(raw);
    k_wprep<<<(144 * 72 + 255) / 256, 256>>>(w2);
    k_f1prep<<<144, 256>>>(fw1);
    k_convfused<<<BATCH, 576, SMEM_CONV>>>(x, w1, b1, b2);
    k_fc1<<<128, 256>>>(fb1);
    k_fc2gmm<<<BATCH / 128, 128, SMEM_GMM>>>(fw2, fb2, cen, out);
}